// round 11
// baseline (speedup 1.0000x reference)
#include <cuda_runtime.h>
#include <cuda_bf16.h>
#include <cstdint>

#define HD 64
#define NB 32
#define BN_TOT (NB*1024)
#define NA_TOT 16384

__device__ float d_xb[BN_TOT*HD];
__device__ float d_A [BN_TOT*HD];   // [b][t][j]
__device__ float d_Y8[NA_TOT*8];
__device__ float d_ge[NB*HD];
__device__ float d_geP[NB*HD];      // probe scratch
__device__ __align__(16) unsigned short d_adjh[NB*1024*1024];  // adj bf16
__device__ __align__(16) unsigned short d_gh[BN_TOT*HD];       // g bf16 [b][node][hd]

__device__ __forceinline__ void ffma2(float2 &c, const float2 a, const float2 b) {
    asm("fma.rn.f32x2 %0, %1, %2, %0;"
        : "+l"(reinterpret_cast<unsigned long long&>(c))
        : "l"(reinterpret_cast<const unsigned long long&>(a)),
          "l"(reinterpret_cast<const unsigned long long&>(b)));
}
__device__ __forceinline__ uint32_t smem_u32(const void* p) {
    uint32_t a;
    asm("{ .reg .u64 t; cvta.to.shared.u64 t, %1; cvt.u32.u64 %0, t; }" : "=r"(a) : "l"(p));
    return a;
}
__device__ __forceinline__ void cp16(uint32_t dst, const void* src) {
    asm volatile("cp.async.cg.shared.global [%0], [%1], 16;" :: "r"(dst), "l"(src));
}
__device__ __forceinline__ void ldm_x4(uint32_t* r, uint32_t addr) {
    asm volatile("ldmatrix.sync.aligned.m8n8.x4.shared.b16 {%0,%1,%2,%3}, [%4];"
        : "=r"(r[0]), "=r"(r[1]), "=r"(r[2]), "=r"(r[3]) : "r"(addr));
}
__device__ __forceinline__ void ldm_x4t(uint32_t* r, uint32_t addr) {
    asm volatile("ldmatrix.sync.aligned.m8n8.x4.trans.shared.b16 {%0,%1,%2,%3}, [%4];"
        : "=r"(r[0]), "=r"(r[1]), "=r"(r[2]), "=r"(r[3]) : "r"(addr));
}
__device__ __forceinline__ void mma_bf16(float* d, const uint32_t* a, const uint32_t* b) {
    asm volatile("mma.sync.aligned.m16n8k16.row.col.f32.bf16.bf16.f32 "
        "{%0,%1,%2,%3}, {%4,%5,%6,%7}, {%8,%9}, {%0,%1,%2,%3};"
        : "+f"(d[0]), "+f"(d[1]), "+f"(d[2]), "+f"(d[3])
        : "r"(a[0]), "r"(a[1]), "r"(a[2]), "r"(a[3]), "r"(b[0]), "r"(b[1]));
}
__device__ __forceinline__ float tanha(float x) {
    float r;
    asm("tanh.approx.f32 %0, %1;" : "=f"(r) : "f"(x));
    return r;
}
__device__ __forceinline__ uint32_t pack_bf2(float x, float y) {
    __nv_bfloat162 p = __floats2bfloat162_rn(x, y);
    return *reinterpret_cast<uint32_t*>(&p);
}

// ---- K1: fused adj->bf16 + init (xb, h0) ----
__global__ void k_prep(const float* __restrict__ adj, const float* __restrict__ x,
                       const float* __restrict__ W1, const float* __restrict__ b1,
                       const float* __restrict__ b2, float* __restrict__ hout) {
    int idx = blockIdx.x * 256 + threadIdx.x;
    const float4* s = (const float4*)adj + (size_t)idx * 2;
    float4 a = s[0], b = s[1];
    uint4 o;
    o.x = pack_bf2(a.x, a.y);
    o.y = pack_bf2(a.z, a.w);
    o.z = pack_bf2(b.x, b.y);
    o.w = pack_bf2(b.z, b.w);
    ((uint4*)d_adjh)[idx] = o;
    if (idx < BN_TOT * HD) {
        int i = idx >> 6, j = idx & 63;
        float2 xv = ((const float2*)x)[i];
        float v = fmaf(xv.x, W1[2*j], fmaf(xv.y, W1[2*j+1], b1[j])) + b2[j];
        d_xb[idx] = v;
        hout[idx] = fmaxf(v, 0.f);
    }
}

// ---- K2: d_gh[b][node][hd] = bf16(in @ W^T) ----
__global__ void __launch_bounds__(128) k_small(const float* __restrict__ in,
                                               const float* __restrict__ W) {
    __shared__ float hsT[64][36];
    __shared__ float Wt[64][68];
    int tid = threadIdx.x;
    int i0 = blockIdx.x * 32;
    for (int idx = tid; idx < 4096; idx += 128)
        Wt[idx & 63][idx >> 6] = W[idx];
    #pragma unroll
    for (int u = 0; u < 4; ++u) {
        int f = tid + 128 * u;
        int r = f >> 4, kc = (f & 15) * 4;
        float4 v = *(const float4*)&in[(i0 + r) * 64 + kc];
        hsT[kc+0][r] = v.x; hsT[kc+1][r] = v.y; hsT[kc+2][r] = v.z; hsT[kc+3][r] = v.w;
    }
    __syncthreads();
    int r4 = (tid & 7) * 4, j4 = (tid >> 3) * 4;
    float2 acc[4][2];
    #pragma unroll
    for (int rr = 0; rr < 4; ++rr) { acc[rr][0] = make_float2(0,0); acc[rr][1] = make_float2(0,0); }
    #pragma unroll 8
    for (int k = 0; k < 64; ++k) {
        float4 a = *(const float4*)&hsT[k][r4];
        float4 w = *(const float4*)&Wt[k][j4];
        float2 w01 = make_float2(w.x, w.y), w23 = make_float2(w.z, w.w);
        ffma2(acc[0][0], w01, make_float2(a.x, a.x));
        ffma2(acc[0][1], w23, make_float2(a.x, a.x));
        ffma2(acc[1][0], w01, make_float2(a.y, a.y));
        ffma2(acc[1][1], w23, make_float2(a.y, a.y));
        ffma2(acc[2][0], w01, make_float2(a.z, a.z));
        ffma2(acc[2][1], w23, make_float2(a.z, a.z));
        ffma2(acc[3][0], w01, make_float2(a.w, a.w));
        ffma2(acc[3][1], w23, make_float2(a.w, a.w));
    }
    int bb = i0 >> 10, rloc = (i0 & 1023) + r4;
    #pragma unroll
    for (int rr = 0; rr < 4; ++rr) {
        uint2 v;
        v.x = pack_bf2(acc[rr][0].x, acc[rr][0].y);
        v.y = pack_bf2(acc[rr][1].x, acc[rr][1].y);
        *(uint2*)&d_gh[(bb * 1024 + rloc + rr) * 64 + j4] = v;
    }
}

// ---- K3: h = relu(xb + adj@g) via bf16 mma; optional fused A epilogue ----
#define ASZB (128*72*2)
#define BSZB (64*72*2)
#define GSMB (2*ASZB + 2*BSZB)   // 55296 B

__global__ void __launch_bounds__(256, 2) k_gnn_bf(float* __restrict__ hout,
        const float* __restrict__ Wih0, const float* __restrict__ bih0,
        const float* __restrict__ bhh0, int writeA) {
    extern __shared__ char smh[];
    uint32_t sA = smem_u32(smh);
    uint32_t sB = sA + 2 * ASZB;
    int tid = threadIdx.x, lane = tid & 31, w = tid >> 5;
    int mt = blockIdx.x, bb = blockIdx.y;
    const char* Abase = (const char*)d_adjh + ((size_t)bb << 21) + ((size_t)mt << 18);
    const char* Bbase = (const char*)d_gh + ((size_t)bb << 17);

    float acc[8][4];
    #pragma unroll
    for (int j = 0; j < 8; ++j)
        #pragma unroll
        for (int q = 0; q < 4; ++q) acc[j][q] = 0.f;

    auto loadA = [&](int buf, int kt) {
        uint32_t dst = sA + buf * ASZB;
        #pragma unroll
        for (int u = 0; u < 4; ++u) {
            int idx = tid + 256 * u;
            int row = idx >> 3, c = idx & 7;
            cp16(dst + row * 144 + c * 16, Abase + (size_t)row * 2048 + kt * 128 + c * 16);
        }
    };
    auto loadB = [&](int buf, int kt) {
        uint32_t dst = sB + buf * BSZB;
        #pragma unroll
        for (int u = 0; u < 2; ++u) {
            int idx = tid + 256 * u;
            int row = idx >> 3, c = idx & 7;
            cp16(dst + row * 144 + c * 16, Bbase + (size_t)(kt * 64 + row) * 128 + c * 16);
        }
    };

    loadA(0, 0); loadB(0, 0);
    asm volatile("cp.async.commit_group;");

    int arow = lane & 15, acol = (lane >> 4) * 8;
    int q = lane >> 3;
    int brow = (lane & 7) + 8 * (q & 1);
    int bcol = 8 * (q >> 1);
    for (int kt = 0; kt < 16; ++kt) {
        int buf = kt & 1;
        if (kt + 1 < 16) {
            loadA(buf ^ 1, kt + 1);
            loadB(buf ^ 1, kt + 1);
            asm volatile("cp.async.commit_group;");
            asm volatile("cp.async.wait_group 1;" ::: "memory");
        } else {
            asm volatile("cp.async.wait_group 0;" ::: "memory");
        }
        __syncthreads();
        uint32_t a0 = sA + buf * ASZB + (16 * w) * 144;
        uint32_t b0 = sB + buf * BSZB;
        #pragma unroll
        for (int ks = 0; ks < 4; ++ks) {
            uint32_t a[4];
            ldm_x4(a, a0 + arow * 144 + (ks * 16 + acol) * 2);
            uint32_t bf[8][2];
            #pragma unroll
            for (int np = 0; np < 4; ++np) {
                uint32_t t4[4];
                ldm_x4t(t4, b0 + (ks * 16 + brow) * 144 + (np * 16 + bcol) * 2);
                bf[2*np][0] = t4[0]; bf[2*np][1] = t4[1];
                bf[2*np+1][0] = t4[2]; bf[2*np+1][1] = t4[3];
            }
            #pragma unroll
            for (int j = 0; j < 8; ++j)
                mma_bf16(acc[j], a, bf[j]);
        }
        __syncthreads();
    }

    int r = lane >> 2, c2 = (lane & 3) * 2;
    size_t row0 = ((size_t)bb << 10) + ((size_t)mt << 7) + 16 * w;
    #pragma unroll
    for (int j = 0; j < 8; ++j) {
        int col = 8 * j + c2;
        size_t o0 = (row0 + r) * 64 + col;
        float2 xb0 = *(const float2*)&d_xb[o0];
        float2 h0;
        h0.x = fmaxf(xb0.x + acc[j][0], 0.f);
        h0.y = fmaxf(xb0.y + acc[j][1], 0.f);
        *(float2*)&hout[o0] = h0;
        size_t o1 = (row0 + r + 8) * 64 + col;
        float2 xb1 = *(const float2*)&d_xb[o1];
        float2 h1;
        h1.x = fmaxf(xb1.x + acc[j][2], 0.f);
        h1.y = fmaxf(xb1.y + acc[j][3], 0.f);
        *(float2*)&hout[o1] = h1;
    }

    if (writeA) {
        float* hs2 = (float*)smh;             // [64][132]
        float* Wt2 = hs2 + 64 * 132;          // [64][68]
        float* bs2 = Wt2 + 64 * 68;           // [64]
        __syncthreads();
        size_t rowg0 = ((size_t)bb << 10) + ((size_t)mt << 7);
        for (int f = tid; f < 2048; f += 256) {
            int rr = f >> 4, kc = (f & 15) * 4;
            float4 v = *(const float4*)&hout[(rowg0 + rr) * 64 + kc];
            hs2[(kc+0) * 132 + rr] = v.x;
            hs2[(kc+1) * 132 + rr] = v.y;
            hs2[(kc+2) * 132 + rr] = v.z;
            hs2[(kc+3) * 132 + rr] = v.w;
        }
        for (int idx = tid; idx < 4096; idx += 256)
            Wt2[(idx & 63) * 68 + (idx >> 6)] = Wih0[idx];
        if (tid < 64) bs2[tid] = bih0[tid] + bhh0[tid];
        __syncthreads();
        int r4 = (tid & 31) * 4, j8 = (tid >> 5) * 8;
        float2 a2[4][4];
        #pragma unroll
        for (int rr = 0; rr < 4; ++rr)
            #pragma unroll
            for (int p = 0; p < 4; ++p) a2[rr][p] = make_float2(0.f, 0.f);
        #pragma unroll 8
        for (int k = 0; k < 64; ++k) {
            float4 hv = *(const float4*)&hs2[k * 132 + r4];
            float4 wa = *(const float4*)&Wt2[k * 68 + j8];
            float4 wb = *(const float4*)&Wt2[k * 68 + j8 + 4];
            float2 w01 = make_float2(wa.x, wa.y), w23 = make_float2(wa.z, wa.w);
            float2 w45 = make_float2(wb.x, wb.y), w67 = make_float2(wb.z, wb.w);
            #pragma unroll
            for (int rr = 0; rr < 4; ++rr) {
                float hvr = (rr == 0) ? hv.x : (rr == 1) ? hv.y : (rr == 2) ? hv.z : hv.w;
                float2 hd = make_float2(hvr, hvr);
                ffma2(a2[rr][0], w01, hd);
                ffma2(a2[rr][1], w23, hd);
                ffma2(a2[rr][2], w45, hd);
                ffma2(a2[rr][3], w67, hd);
            }
        }
        float* Aout = d_A + ((size_t)bb << 16) + ((size_t)(mt * 128)) * 64;
        #pragma unroll
        for (int rr = 0; rr < 4; ++rr) {
            float4 v1, v2;
            v1.x = a2[rr][0].x + bs2[j8+0];
            v1.y = a2[rr][0].y + bs2[j8+1];
            v1.z = a2[rr][1].x + bs2[j8+2];
            v1.w = a2[rr][1].y + bs2[j8+3];
            v2.x = a2[rr][2].x + bs2[j8+4];
            v2.y = a2[rr][2].y + bs2[j8+5];
            v2.z = a2[rr][3].x + bs2[j8+6];
            v2.w = a2[rr][3].y + bs2[j8+7];
            *(float4*)&Aout[(r4 + rr) * 64 + j8] = v1;
            *(float4*)&Aout[(r4 + rr) * 64 + j8 + 4] = v2;
        }
    }
}

// ---- K4: scan (nsteps-parameterized: real run = 1024 -> d_ge; probe = 128 -> d_geP) ----
__global__ void __launch_bounds__(224, 1) k_scan4(const float* __restrict__ Whh0,
        const float* __restrict__ Wih1, const float* __restrict__ Whh1,
        const float* __restrict__ bih1, const float* __restrict__ bhh1,
        const float* __restrict__ Wt6, const float* __restrict__ bt6,
        int nsteps, float* __restrict__ geo) {
    __shared__ float S[4][64];
    __shared__ float Abuf[8][64];
    __shared__ float bsum[64];
    int b = blockIdx.x, tid = threadIdx.x;
    for (int i = tid; i < 256; i += 224) ((float*)S)[i] = 0.f;
    if (tid < 64) bsum[tid] = bih1[tid] + bhh1[tid];
    const float* Ab = d_A + ((size_t)b << 16);

    float2 w[32];
    int j = 0, part = 0;
    float2 avreg = make_float2(0.f, 0.f);
    if (tid < 64) {
        j = tid;
        const float2* wr = (const float2*)(Whh0 + j * 64);
        #pragma unroll
        for (int kk = 0; kk < 32; ++kk) w[kk] = wr[kk];
    } else if (tid < 192) {
        int lt = tid - 64, lane = lt & 31, wg = lt >> 5;
        j = wg * 16 + (lane & 15);
        part = lane >> 4;
        const float2* wr = (const float2*)((part == 0 ? Wih1 : Whh1) + j * 64);
        #pragma unroll
        for (int kk = 0; kk < 32; ++kk) w[kk] = wr[kk];
    } else {
        int lane = tid - 192;
        #pragma unroll
        for (int u = 0; u < 4; ++u)
            *(float2*)&Abuf[u][lane * 2] = *(const float2*)&Ab[u * 64 + lane * 2];
        avreg = *(const float2*)&Ab[4 * 64 + lane * 2];
    }
    __syncthreads();

    int pc = 0;
    for (int t = 0; t <= nsteps; ++t) {
        if (tid < 64) {
            if (t < nsteps) {
                float at = Abuf[t & 7][j];
                float2 a0 = {0,0}, a1 = {0,0}, a2 = {0,0}, a3 = {0,0};
                const float4* c4 = (const float4*)&S[pc][0];
                #pragma unroll
                for (int qq = 0; qq < 8; ++qq) {
                    float4 cv0 = c4[2*qq], cv1 = c4[2*qq+1];
                    ffma2(a0, w[4*qq+0], make_float2(cv0.x, cv0.y));
                    ffma2(a1, w[4*qq+1], make_float2(cv0.z, cv0.w));
                    ffma2(a2, w[4*qq+2], make_float2(cv1.x, cv1.y));
                    ffma2(a3, w[4*qq+3], make_float2(cv1.z, cv1.w));
                }
                float sx = (a0.x + a1.x) + (a2.x + a3.x);
                float sy = (a0.y + a1.y) + (a2.y + a3.y);
                S[pc ^ 1][j] = tanha(sx + sy + at);
            }
        } else if (tid < 192) {
            const float4* c4 = (const float4*)&S[part ? (2 + pc) : pc][0];
            float2 a0 = {0,0}, a1 = {0,0}, a2 = {0,0}, a3 = {0,0};
            #pragma unroll
            for (int qq = 0; qq < 8; ++qq) {
                float4 cv0 = c4[2*qq], cv1 = c4[2*qq+1];
                ffma2(a0, w[4*qq+0], make_float2(cv0.x, cv0.y));
                ffma2(a1, w[4*qq+1], make_float2(cv0.z, cv0.w));
                ffma2(a2, w[4*qq+2], make_float2(cv1.x, cv1.y));
                ffma2(a3, w[4*qq+3], make_float2(cv1.z, cv1.w));
            }
            float ps = ((a0.x + a1.x) + (a2.x + a3.x)) + ((a0.y + a1.y) + (a2.y + a3.y));
            float full = ps + __shfl_xor_sync(0xffffffffu, ps, 16);
            if (part == 0) {
                S[2 + (pc ^ 1)][j] = (t == 0) ? 0.f : tanha(full + bsum[j]);
            }
        } else {
            int lane = tid - 192;
            *(float2*)&Abuf[(t + 4) & 7][lane * 2] = avreg;
            int tt = t + 5;
            if (tt < nsteps)
                avreg = *(const float2*)&Ab[tt * 64 + lane * 2];
        }
        __syncthreads();
        pc ^= 1;
    }
    if (tid < 64) {
        float acc = bt6[j];
        const float* cf = S[2 + pc];
        #pragma unroll 8
        for (int k = 0; k < 64; ++k) acc = fmaf(cf[k], Wt6[j * 64 + k], acc);
        geo[b * 64 + j] = acc;
    }
}

// ---- K5: gather + R + Y8 ----
__global__ void k_r(const int* __restrict__ label, const int* __restrict__ actions,
                    const float* __restrict__ x, float* __restrict__ Rout) {
    int a = blockIdx.x * 256 + threadIdx.x;
    int b = a >> 9;
    int i0 = actions[2 * a], i1 = actions[2 * a + 1];
    const int* lb = label + (b << 10);
    int a0 = lb[i0], a1 = lb[i1];
    int li = lb[(i0 + 1023) & 1023], ri = lb[(i1 + 1) & 1023];
    int off = b << 10;
    const float2* xv = (const float2*)x;
    float2 y0 = xv[a0 + off], y1 = xv[a1 + off], y2 = xv[li + off], y3 = xv[ri + off];
    float d02x = y0.x - y2.x, d02y = y0.y - y2.y;
    float d13x = y1.x - y3.x, d13y = y1.y - y3.y;
    float d12x = y1.x - y2.x, d12y = y1.y - y2.y;
    float d03x = y0.x - y3.x, d03y = y0.y - y3.y;
    float R = sqrtf(fmaf(d02x, d02x, d02y * d02y)) + sqrtf(fmaf(d13x, d13x, d13y * d13y))
            - sqrtf(fmaf(d12x, d12x, d12y * d12y)) - sqrtf(fmaf(d03x, d03x, d03y * d03y));
    Rout[a] = R;
    float4* Y = (float4*)(d_Y8 + a * 8);
    Y[0] = make_float4(y0.x, y0.y, y1.x, y1.y);
    Y[1] = make_float4(y2.x, y2.y, y3.x, y3.y);
}

// ---- K6: feat + Q ----
__global__ void k_q(const float* __restrict__ WL, const float* __restrict__ bL,
                    const float* __restrict__ Wt5, const float* __restrict__ bt5,
                    const float* __restrict__ R, float* __restrict__ Q) {
    __shared__ float ges[64], WLs[512], bLs[64], w5[65];
    int b = blockIdx.x, a = threadIdx.x;
    if (a < 64) { ges[a] = d_ge[b * 64 + a]; bLs[a] = bL[a]; w5[a] = Wt5[a]; }
    if (a == 64) w5[64] = Wt5[64];
    WLs[a] = WL[a];
    __syncthreads();
    int ba = b * 512 + a;
    float4 y0 = *(const float4*)&d_Y8[ba * 8];
    float4 y1 = *(const float4*)&d_Y8[ba * 8 + 4];
    float y[8] = {y0.x, y0.y, y0.z, y0.w, y1.x, y1.y, y1.z, y1.w};
    float q = 0.f;
    #pragma unroll 8
    for (int jj = 0; jj < 64; ++jj) {
        float f = ges[jj] + bLs[jj];
        #pragma unroll
        for (int m = 0; m < 8; ++m) f = fmaf(y[m], WLs[jj * 8 + m], f);
        q = fmaf(fmaxf(f, 0.f), w5[jj], q);
    }
    Q[ba] = fmaf(R[ba], w5[64], q) + bt5[0];
}

extern "C" void kernel_launch(void* const* d_in, const int* in_sizes, int n_in,
                              void* d_out, int out_size) {
    const float* adj  = (const float*)d_in[0];
    const float* x    = (const float*)d_in[1];
    const int*  label = (const int*)  d_in[2];
    const int*  acts  = (const int*)  d_in[3];
    const float* W1   = (const float*)d_in[4];
    const float* b1   = (const float*)d_in[5];
    const float* W2   = (const float*)d_in[6];
    const float* b2   = (const float*)d_in[7];
    const float* Wih0 = (const float*)d_in[8];
    const float* bih0 = (const float*)d_in[9];
    const float* Whh0 = (const float*)d_in[10];
    const float* bhh0 = (const float*)d_in[11];
    const float* Wih1 = (const float*)d_in[12];
    const float* bih1 = (const float*)d_in[13];
    const float* Whh1 = (const float*)d_in[14];
    const float* bhh1 = (const float*)d_in[15];
    const float* Wt6  = (const float*)d_in[16];
    const float* bt6  = (const float*)d_in[17];
    const float* WL   = (const float*)d_in[18];
    const float* bL   = (const float*)d_in[19];
    const float* Wt5  = (const float*)d_in[20];
    const float* bt5  = (const float*)d_in[21];

    float* out  = (float*)d_out;
    float* Rout = out;
    float* hout = out + 16384;
    float* Qout = out + 16384 + BN_TOT * HD;

    float* geP;
    cudaGetSymbolAddress((void**)&geP, d_geP);
    float* geR;
    cudaGetSymbolAddress((void**)&geR, d_ge);

    cudaFuncSetAttribute(k_gnn_bf, cudaFuncAttributeMaxDynamicSharedMemorySize, GSMB);

    k_prep<<<16384, 256>>>(adj, x, W1, b1, b2, hout);                     // 1
    k_small<<<1024, 128>>>(hout, W2);                                     // 2
    k_gnn_bf<<<dim3(8, 32), 256, GSMB>>>(hout, Wih0, bih0, bhh0, 0);      // 3
    // 4: PROBE — identical scan kernel, 128 steps, scratch output (ncu slot = launch #4)
    k_scan4<<<32, 224>>>(Whh0, Wih1, Whh1, bih1, bhh1, Wt6, bt6, 128, geP);
    k_small<<<1024, 128>>>(hout, W2);                                     // 5
    k_gnn_bf<<<dim3(8, 32), 256, GSMB>>>(hout, Wih0, bih0, bhh0, 1);      // 6
    k_scan4<<<32, 224>>>(Whh0, Wih1, Whh1, bih1, bhh1, Wt6, bt6, 1024, geR); // 7
    k_r<<<64, 256>>>(label, acts, x, Rout);                               // 8
    k_q<<<32, 512>>>(WL, bL, Wt5, bt5, Rout, Qout);                       // 9
}

// round 12
// speedup vs baseline: 1.0014x; 1.0014x over previous
#include <cuda_runtime.h>
#include <cuda_bf16.h>
#include <cstdint>

#define HD 64
#define NB 32
#define BN_TOT (NB*1024)
#define NA_TOT 16384

__device__ float d_xb[BN_TOT*HD];
__device__ float d_A [BN_TOT*HD];   // [b][t][j]
__device__ float d_Y8[NA_TOT*8];
__device__ float d_ge[NB*HD];
__device__ __align__(16) unsigned short d_adjh[NB*1024*1024];  // adj bf16
__device__ __align__(16) unsigned short d_gh[BN_TOT*HD];       // g bf16 [b][node][hd]

__device__ __forceinline__ void ffma2(float2 &c, const float2 a, const float2 b) {
    asm("fma.rn.f32x2 %0, %1, %2, %0;"
        : "+l"(reinterpret_cast<unsigned long long&>(c))
        : "l"(reinterpret_cast<const unsigned long long&>(a)),
          "l"(reinterpret_cast<const unsigned long long&>(b)));
}
__device__ __forceinline__ uint32_t smem_u32(const void* p) {
    uint32_t a;
    asm("{ .reg .u64 t; cvta.to.shared.u64 t, %1; cvt.u32.u64 %0, t; }" : "=r"(a) : "l"(p));
    return a;
}
__device__ __forceinline__ void cp16(uint32_t dst, const void* src) {
    asm volatile("cp.async.cg.shared.global [%0], [%1], 16;" :: "r"(dst), "l"(src));
}
__device__ __forceinline__ void ldm_x4(uint32_t* r, uint32_t addr) {
    asm volatile("ldmatrix.sync.aligned.m8n8.x4.shared.b16 {%0,%1,%2,%3}, [%4];"
        : "=r"(r[0]), "=r"(r[1]), "=r"(r[2]), "=r"(r[3]) : "r"(addr));
}
__device__ __forceinline__ void ldm_x4t(uint32_t* r, uint32_t addr) {
    asm volatile("ldmatrix.sync.aligned.m8n8.x4.trans.shared.b16 {%0,%1,%2,%3}, [%4];"
        : "=r"(r[0]), "=r"(r[1]), "=r"(r[2]), "=r"(r[3]) : "r"(addr));
}
__device__ __forceinline__ void mma_bf16(float* d, const uint32_t* a, const uint32_t* b) {
    asm volatile("mma.sync.aligned.m16n8k16.row.col.f32.bf16.bf16.f32 "
        "{%0,%1,%2,%3}, {%4,%5,%6,%7}, {%8,%9}, {%0,%1,%2,%3};"
        : "+f"(d[0]), "+f"(d[1]), "+f"(d[2]), "+f"(d[3])
        : "r"(a[0]), "r"(a[1]), "r"(a[2]), "r"(a[3]), "r"(b[0]), "r"(b[1]));
}
__device__ __forceinline__ float tanha(float x) {
    float r;
    asm("tanh.approx.f32 %0, %1;" : "=f"(r) : "f"(x));
    return r;
}
__device__ __forceinline__ uint32_t pack_bf2(float x, float y) {
    __nv_bfloat162 p = __floats2bfloat162_rn(x, y);
    return *reinterpret_cast<uint32_t*>(&p);
}

// ---- K1: fused adj->bf16 + init (xb, h0) ----
__global__ void k_prep(const float* __restrict__ adj, const float* __restrict__ x,
                       const float* __restrict__ W1, const float* __restrict__ b1,
                       const float* __restrict__ b2, float* __restrict__ hout) {
    int idx = blockIdx.x * 256 + threadIdx.x;
    const float4* s = (const float4*)adj + (size_t)idx * 2;
    float4 a = s[0], b = s[1];
    uint4 o;
    o.x = pack_bf2(a.x, a.y);
    o.y = pack_bf2(a.z, a.w);
    o.z = pack_bf2(b.x, b.y);
    o.w = pack_bf2(b.z, b.w);
    ((uint4*)d_adjh)[idx] = o;
    if (idx < BN_TOT * HD) {
        int i = idx >> 6, j = idx & 63;
        float2 xv = ((const float2*)x)[i];
        float v = fmaf(xv.x, W1[2*j], fmaf(xv.y, W1[2*j+1], b1[j])) + b2[j];
        d_xb[idx] = v;
        hout[idx] = fmaxf(v, 0.f);
    }
}

// ---- K2: d_gh[b][node][hd] = bf16(in @ W^T) ----
__global__ void __launch_bounds__(128) k_small(const float* __restrict__ in,
                                               const float* __restrict__ W) {
    __shared__ float hsT[64][36];
    __shared__ float Wt[64][68];
    int tid = threadIdx.x;
    int i0 = blockIdx.x * 32;
    for (int idx = tid; idx < 4096; idx += 128)
        Wt[idx & 63][idx >> 6] = W[idx];
    #pragma unroll
    for (int u = 0; u < 4; ++u) {
        int f = tid + 128 * u;
        int r = f >> 4, kc = (f & 15) * 4;
        float4 v = *(const float4*)&in[(i0 + r) * 64 + kc];
        hsT[kc+0][r] = v.x; hsT[kc+1][r] = v.y; hsT[kc+2][r] = v.z; hsT[kc+3][r] = v.w;
    }
    __syncthreads();
    int r4 = (tid & 7) * 4, j4 = (tid >> 3) * 4;
    float2 acc[4][2];
    #pragma unroll
    for (int rr = 0; rr < 4; ++rr) { acc[rr][0] = make_float2(0,0); acc[rr][1] = make_float2(0,0); }
    #pragma unroll 8
    for (int k = 0; k < 64; ++k) {
        float4 a = *(const float4*)&hsT[k][r4];
        float4 w = *(const float4*)&Wt[k][j4];
        float2 w01 = make_float2(w.x, w.y), w23 = make_float2(w.z, w.w);
        ffma2(acc[0][0], w01, make_float2(a.x, a.x));
        ffma2(acc[0][1], w23, make_float2(a.x, a.x));
        ffma2(acc[1][0], w01, make_float2(a.y, a.y));
        ffma2(acc[1][1], w23, make_float2(a.y, a.y));
        ffma2(acc[2][0], w01, make_float2(a.z, a.z));
        ffma2(acc[2][1], w23, make_float2(a.z, a.z));
        ffma2(acc[3][0], w01, make_float2(a.w, a.w));
        ffma2(acc[3][1], w23, make_float2(a.w, a.w));
    }
    int bb = i0 >> 10, rloc = (i0 & 1023) + r4;
    #pragma unroll
    for (int rr = 0; rr < 4; ++rr) {
        uint2 v;
        v.x = pack_bf2(acc[rr][0].x, acc[rr][0].y);
        v.y = pack_bf2(acc[rr][1].x, acc[rr][1].y);
        *(uint2*)&d_gh[(bb * 1024 + rloc + rr) * 64 + j4] = v;
    }
}

// ---- K3: h = relu(xb + adj@g) via bf16 mma; optional fused A epilogue ----
#define ASZB (128*72*2)
#define BSZB (64*72*2)
#define GSMB (2*ASZB + 2*BSZB)   // 55296 B

__global__ void __launch_bounds__(256, 2) k_gnn_bf(float* __restrict__ hout,
        const float* __restrict__ Wih0, const float* __restrict__ bih0,
        const float* __restrict__ bhh0, int writeA) {
    extern __shared__ char smh[];
    uint32_t sA = smem_u32(smh);
    uint32_t sB = sA + 2 * ASZB;
    int tid = threadIdx.x, lane = tid & 31, w = tid >> 5;
    int mt = blockIdx.x, bb = blockIdx.y;
    const char* Abase = (const char*)d_adjh + ((size_t)bb << 21) + ((size_t)mt << 18);
    const char* Bbase = (const char*)d_gh + ((size_t)bb << 17);

    float acc[8][4];
    #pragma unroll
    for (int j = 0; j < 8; ++j)
        #pragma unroll
        for (int q = 0; q < 4; ++q) acc[j][q] = 0.f;

    auto loadA = [&](int buf, int kt) {
        uint32_t dst = sA + buf * ASZB;
        #pragma unroll
        for (int u = 0; u < 4; ++u) {
            int idx = tid + 256 * u;
            int row = idx >> 3, c = idx & 7;
            cp16(dst + row * 144 + c * 16, Abase + (size_t)row * 2048 + kt * 128 + c * 16);
        }
    };
    auto loadB = [&](int buf, int kt) {
        uint32_t dst = sB + buf * BSZB;
        #pragma unroll
        for (int u = 0; u < 2; ++u) {
            int idx = tid + 256 * u;
            int row = idx >> 3, c = idx & 7;
            cp16(dst + row * 144 + c * 16, Bbase + (size_t)(kt * 64 + row) * 128 + c * 16);
        }
    };

    loadA(0, 0); loadB(0, 0);
    asm volatile("cp.async.commit_group;");

    int arow = lane & 15, acol = (lane >> 4) * 8;
    int q = lane >> 3;
    int brow = (lane & 7) + 8 * (q & 1);
    int bcol = 8 * (q >> 1);
    for (int kt = 0; kt < 16; ++kt) {
        int buf = kt & 1;
        if (kt + 1 < 16) {
            loadA(buf ^ 1, kt + 1);
            loadB(buf ^ 1, kt + 1);
            asm volatile("cp.async.commit_group;");
            asm volatile("cp.async.wait_group 1;" ::: "memory");
        } else {
            asm volatile("cp.async.wait_group 0;" ::: "memory");
        }
        __syncthreads();
        uint32_t a0 = sA + buf * ASZB + (16 * w) * 144;
        uint32_t b0 = sB + buf * BSZB;
        #pragma unroll
        for (int ks = 0; ks < 4; ++ks) {
            uint32_t a[4];
            ldm_x4(a, a0 + arow * 144 + (ks * 16 + acol) * 2);
            uint32_t bf[8][2];
            #pragma unroll
            for (int np = 0; np < 4; ++np) {
                uint32_t t4[4];
                ldm_x4t(t4, b0 + (ks * 16 + brow) * 144 + (np * 16 + bcol) * 2);
                bf[2*np][0] = t4[0]; bf[2*np][1] = t4[1];
                bf[2*np+1][0] = t4[2]; bf[2*np+1][1] = t4[3];
            }
            #pragma unroll
            for (int j = 0; j < 8; ++j)
                mma_bf16(acc[j], a, bf[j]);
        }
        __syncthreads();
    }

    int r = lane >> 2, c2 = (lane & 3) * 2;
    size_t row0 = ((size_t)bb << 10) + ((size_t)mt << 7) + 16 * w;
    #pragma unroll
    for (int j = 0; j < 8; ++j) {
        int col = 8 * j + c2;
        size_t o0 = (row0 + r) * 64 + col;
        float2 xb0 = *(const float2*)&d_xb[o0];
        float2 h0;
        h0.x = fmaxf(xb0.x + acc[j][0], 0.f);
        h0.y = fmaxf(xb0.y + acc[j][1], 0.f);
        *(float2*)&hout[o0] = h0;
        size_t o1 = (row0 + r + 8) * 64 + col;
        float2 xb1 = *(const float2*)&d_xb[o1];
        float2 h1;
        h1.x = fmaxf(xb1.x + acc[j][2], 0.f);
        h1.y = fmaxf(xb1.y + acc[j][3], 0.f);
        *(float2*)&hout[o1] = h1;
    }

    if (writeA) {
        float* hs2 = (float*)smh;             // [64][132]
        float* Wt2 = hs2 + 64 * 132;          // [64][68]
        float* bs2 = Wt2 + 64 * 68;           // [64]
        __syncthreads();
        size_t rowg0 = ((size_t)bb << 10) + ((size_t)mt << 7);
        for (int f = tid; f < 2048; f += 256) {
            int rr = f >> 4, kc = (f & 15) * 4;
            float4 v = *(const float4*)&hout[(rowg0 + rr) * 64 + kc];
            hs2[(kc+0) * 132 + rr] = v.x;
            hs2[(kc+1) * 132 + rr] = v.y;
            hs2[(kc+2) * 132 + rr] = v.z;
            hs2[(kc+3) * 132 + rr] = v.w;
        }
        for (int idx = tid; idx < 4096; idx += 256)
            Wt2[(idx & 63) * 68 + (idx >> 6)] = Wih0[idx];
        if (tid < 64) bs2[tid] = bih0[tid] + bhh0[tid];
        __syncthreads();
        int r4 = (tid & 31) * 4, j8 = (tid >> 5) * 8;
        float2 a2[4][4];
        #pragma unroll
        for (int rr = 0; rr < 4; ++rr)
            #pragma unroll
            for (int p = 0; p < 4; ++p) a2[rr][p] = make_float2(0.f, 0.f);
        #pragma unroll 8
        for (int k = 0; k < 64; ++k) {
            float4 hv = *(const float4*)&hs2[k * 132 + r4];
            float4 wa = *(const float4*)&Wt2[k * 68 + j8];
            float4 wb = *(const float4*)&Wt2[k * 68 + j8 + 4];
            float2 w01 = make_float2(wa.x, wa.y), w23 = make_float2(wa.z, wa.w);
            float2 w45 = make_float2(wb.x, wb.y), w67 = make_float2(wb.z, wb.w);
            #pragma unroll
            for (int rr = 0; rr < 4; ++rr) {
                float hvr = (rr == 0) ? hv.x : (rr == 1) ? hv.y : (rr == 2) ? hv.z : hv.w;
                float2 hd = make_float2(hvr, hvr);
                ffma2(a2[rr][0], w01, hd);
                ffma2(a2[rr][1], w23, hd);
                ffma2(a2[rr][2], w45, hd);
                ffma2(a2[rr][3], w67, hd);
            }
        }
        float* Aout = d_A + ((size_t)bb << 16) + ((size_t)(mt * 128)) * 64;
        #pragma unroll
        for (int rr = 0; rr < 4; ++rr) {
            float4 v1, v2;
            v1.x = a2[rr][0].x + bs2[j8+0];
            v1.y = a2[rr][0].y + bs2[j8+1];
            v1.z = a2[rr][1].x + bs2[j8+2];
            v1.w = a2[rr][1].y + bs2[j8+3];
            v2.x = a2[rr][2].x + bs2[j8+4];
            v2.y = a2[rr][2].y + bs2[j8+5];
            v2.z = a2[rr][3].x + bs2[j8+6];
            v2.w = a2[rr][3].y + bs2[j8+7];
            *(float4*)&Aout[(r4 + rr) * 64 + j8] = v1;
            *(float4*)&Aout[(r4 + rr) * 64 + j8 + 4] = v2;
        }
    }
}

// ---- K4: scan, 8 balanced warps: w0-3 layer1, w4-7 layer0 (k-split) + prefetch ----
__global__ void __launch_bounds__(256, 1) k_scan5(const float* __restrict__ Whh0,
        const float* __restrict__ Wih1, const float* __restrict__ Whh1,
        const float* __restrict__ bih1, const float* __restrict__ bhh1,
        const float* __restrict__ Wt6, const float* __restrict__ bt6) {
    __shared__ float S[4][64];
    __shared__ float Abuf[8][64];
    __shared__ float bsum[64];
    int b = blockIdx.x, tid = threadIdx.x;
    int wid = tid >> 5, lane = tid & 31;
    for (int i = tid; i < 256; i += 256) ((float*)S)[i] = 0.f;
    if (tid < 64) bsum[tid] = bih1[tid] + bhh1[tid];
    const float* Ab = d_A + ((size_t)b << 16);

    int j, part;
    float2 avreg = make_float2(0.f, 0.f);
    int pf = 0, pidx = 0;
    float2 w[32];
    if (wid < 4) {
        // layer1: j per (warp, lane&15); part0 = Wih1 . c0, part1 = Whh1 . c1 (full k)
        j = wid * 16 + (lane & 15);
        part = lane >> 4;
        const float2* wr = (const float2*)((part == 0 ? Wih1 : Whh1) + j * 64);
        #pragma unroll
        for (int kk = 0; kk < 32; ++kk) w[kk] = wr[kk];
    } else {
        // layer0: j per (warp-4, lane&15); part = k-half; 16 ffma2
        j = (wid - 4) * 16 + (lane & 15);
        part = lane >> 4;
        const float2* wr = (const float2*)(Whh0 + j * 64 + part * 32);
        #pragma unroll
        for (int kk = 0; kk < 16; ++kk) w[kk] = wr[kk];
        // prefetch duty: warps 4,5 part1 lanes handle A[t+4] ring (32 float2 = 64 floats)
        pf = (wid < 6) && (part == 1);
        pidx = (wid - 4) * 16 + (lane & 15);     // 0..31
        if (pf) {
            #pragma unroll
            for (int u = 0; u < 4; ++u)
                *(float2*)&Abuf[u][pidx * 2] = *(const float2*)&Ab[u * 64 + pidx * 2];
            avreg = *(const float2*)&Ab[4 * 64 + pidx * 2];
        }
    }
    __syncthreads();

    int pc = 0;
    for (int t = 0; t <= 1024; ++t) {
        if (wid < 4) {
            // layer1: c1[t-1] = tanh(Wih1.c0[t-1] + Whh1.c1[t-2] + b)
            const float4* c4 = (const float4*)&S[part ? (2 + pc) : pc][0];
            float2 a0 = {0,0}, a1 = {0,0}, a2 = {0,0}, a3 = {0,0};
            #pragma unroll
            for (int qq = 0; qq < 8; ++qq) {
                float4 cv0 = c4[2*qq], cv1 = c4[2*qq+1];
                ffma2(a0, w[4*qq+0], make_float2(cv0.x, cv0.y));
                ffma2(a1, w[4*qq+1], make_float2(cv0.z, cv0.w));
                ffma2(a2, w[4*qq+2], make_float2(cv1.x, cv1.y));
                ffma2(a3, w[4*qq+3], make_float2(cv1.z, cv1.w));
            }
            float ps = ((a0.x + a1.x) + (a2.x + a3.x)) + ((a0.y + a1.y) + (a2.y + a3.y));
            float full = ps + __shfl_xor_sync(0xffffffffu, ps, 16);
            if (part == 0)
                S[2 + (pc ^ 1)][j] = (t == 0) ? 0.f : tanha(full + bsum[j]);
        } else {
            if (t < 1024) {
                // layer0: c0[t] = tanh(Whh0.c0[t-1] + A[t]); k-split halves
                const float4* c4 = (const float4*)&S[pc][part * 32];
                float2 a0 = {0,0}, a1 = {0,0}, a2 = {0,0}, a3 = {0,0};
                #pragma unroll
                for (int qq = 0; qq < 4; ++qq) {
                    float4 cv0 = c4[2*qq], cv1 = c4[2*qq+1];
                    ffma2(a0, w[4*qq+0], make_float2(cv0.x, cv0.y));
                    ffma2(a1, w[4*qq+1], make_float2(cv0.z, cv0.w));
                    ffma2(a2, w[4*qq+2], make_float2(cv1.x, cv1.y));
                    ffma2(a3, w[4*qq+3], make_float2(cv1.z, cv1.w));
                }
                float ps = ((a0.x + a1.x) + (a2.x + a3.x)) + ((a0.y + a1.y) + (a2.y + a3.y));
                float full = ps + __shfl_xor_sync(0xffffffffu, ps, 16);
                if (part == 0) {
                    float at = Abuf[t & 7][j];
                    S[pc ^ 1][j] = tanha(full + at);
                } else if (pf) {
                    *(float2*)&Abuf[(t + 4) & 7][pidx * 2] = avreg;
                    int tt = t + 5;
                    if (tt < 1024)
                        avreg = *(const float2*)&Ab[tt * 64 + pidx * 2];
                }
            }
        }
        __syncthreads();
        pc ^= 1;
    }
    if (tid < 64) {
        float acc = bt6[tid];
        const float* cf = S[2 + pc];
        #pragma unroll 8
        for (int k = 0; k < 64; ++k) acc = fmaf(cf[k], Wt6[tid * 64 + k], acc);
        d_ge[b * 64 + tid] = acc;
    }
}

// ---- K5: gather + R + Y8 ----
__global__ void k_r(const int* __restrict__ label, const int* __restrict__ actions,
                    const float* __restrict__ x, float* __restrict__ Rout) {
    int a = blockIdx.x * 256 + threadIdx.x;
    int b = a >> 9;
    int i0 = actions[2 * a], i1 = actions[2 * a + 1];
    const int* lb = label + (b << 10);
    int a0 = lb[i0], a1 = lb[i1];
    int li = lb[(i0 + 1023) & 1023], ri = lb[(i1 + 1) & 1023];
    int off = b << 10;
    const float2* xv = (const float2*)x;
    float2 y0 = xv[a0 + off], y1 = xv[a1 + off], y2 = xv[li + off], y3 = xv[ri + off];
    float d02x = y0.x - y2.x, d02y = y0.y - y2.y;
    float d13x = y1.x - y3.x, d13y = y1.y - y3.y;
    float d12x = y1.x - y2.x, d12y = y1.y - y2.y;
    float d03x = y0.x - y3.x, d03y = y0.y - y3.y;
    float R = sqrtf(fmaf(d02x, d02x, d02y * d02y)) + sqrtf(fmaf(d13x, d13x, d13y * d13y))
            - sqrtf(fmaf(d12x, d12x, d12y * d12y)) - sqrtf(fmaf(d03x, d03x, d03y * d03y));
    Rout[a] = R;
    float4* Y = (float4*)(d_Y8 + a * 8);
    Y[0] = make_float4(y0.x, y0.y, y1.x, y1.y);
    Y[1] = make_float4(y2.x, y2.y, y3.x, y3.y);
}

// ---- K6: feat + Q ----
__global__ void k_q(const float* __restrict__ WL, const float* __restrict__ bL,
                    const float* __restrict__ Wt5, const float* __restrict__ bt5,
                    const float* __restrict__ R, float* __restrict__ Q) {
    __shared__ float ges[64], WLs[512], bLs[64], w5[65];
    int b = blockIdx.x, a = threadIdx.x;
    if (a < 64) { ges[a] = d_ge[b * 64 + a]; bLs[a] = bL[a]; w5[a] = Wt5[a]; }
    if (a == 64) w5[64] = Wt5[64];
    WLs[a] = WL[a];
    __syncthreads();
    int ba = b * 512 + a;
    float4 y0 = *(const float4*)&d_Y8[ba * 8];
    float4 y1 = *(const float4*)&d_Y8[ba * 8 + 4];
    float y[8] = {y0.x, y0.y, y0.z, y0.w, y1.x, y1.y, y1.z, y1.w};
    float q = 0.f;
    #pragma unroll 8
    for (int jj = 0; jj < 64; ++jj) {
        float f = ges[jj] + bLs[jj];
        #pragma unroll
        for (int m = 0; m < 8; ++m) f = fmaf(y[m], WLs[jj * 8 + m], f);
        q = fmaf(fmaxf(f, 0.f), w5[jj], q);
    }
    Q[ba] = fmaf(R[ba], w5[64], q) + bt5[0];
}

extern "C" void kernel_launch(void* const* d_in, const int* in_sizes, int n_in,
                              void* d_out, int out_size) {
    const float* adj  = (const float*)d_in[0];
    const float* x    = (const float*)d_in[1];
    const int*  label = (const int*)  d_in[2];
    const int*  acts  = (const int*)  d_in[3];
    const float* W1   = (const float*)d_in[4];
    const float* b1   = (const float*)d_in[5];
    const float* W2   = (const float*)d_in[6];
    const float* b2   = (const float*)d_in[7];
    const float* Wih0 = (const float*)d_in[8];
    const float* bih0 = (const float*)d_in[9];
    const float* Whh0 = (const float*)d_in[10];
    const float* bhh0 = (const float*)d_in[11];
    const float* Wih1 = (const float*)d_in[12];
    const float* bih1 = (const float*)d_in[13];
    const float* Whh1 = (const float*)d_in[14];
    const float* bhh1 = (const float*)d_in[15];
    const float* Wt6  = (const float*)d_in[16];
    const float* bt6  = (const float*)d_in[17];
    const float* WL   = (const float*)d_in[18];
    const float* bL   = (const float*)d_in[19];
    const float* Wt5  = (const float*)d_in[20];
    const float* bt5  = (const float*)d_in[21];

    float* out  = (float*)d_out;
    float* Rout = out;
    float* hout = out + 16384;
    float* Qout = out + 16384 + BN_TOT * HD;

    cudaFuncSetAttribute(k_gnn_bf, cudaFuncAttributeMaxDynamicSharedMemorySize, GSMB);

    k_prep<<<16384, 256>>>(adj, x, W1, b1, b2, hout);                     // 1
    k_small<<<1024, 128>>>(hout, W2);                                     // 2
    k_gnn_bf<<<dim3(8, 32), 256, GSMB>>>(hout, Wih0, bih0, bhh0, 0);      // 3
    k_small<<<1024, 128>>>(hout, W2);                                     // 4
    k_gnn_bf<<<dim3(8, 32), 256, GSMB>>>(hout, Wih0, bih0, bhh0, 1);      // 5
    k_scan5<<<32, 256>>>(Whh0, Wih1, Whh1, bih1, bhh1, Wt6, bt6);         // 6
    k_r<<<64, 256>>>(label, acts, x, Rout);                               // 7
    k_q<<<32, 512>>>(WL, bL, Wt5, bt5, Rout, Qout);                       // 8
}

// round 13
// speedup vs baseline: 1.5887x; 1.5864x over previous
#include <cuda_runtime.h>
#include <cuda_bf16.h>
#include <cstdint>

#define HD 64
#define NB 32
#define BN_TOT (NB*1024)
#define NA_TOT 16384

__device__ float d_xb[BN_TOT*HD];
__device__ float d_A [BN_TOT*HD];   // [b][t][j]
__device__ float d_Y8[NA_TOT*8];
__device__ float d_ge[NB*HD];
__device__ __align__(16) unsigned short d_adjh[NB*1024*1024];  // adj bf16
__device__ __align__(16) unsigned short d_gh[BN_TOT*HD];       // g bf16 [b][node][hd]

__device__ __forceinline__ void ffma2(float2 &c, const float2 a, const float2 b) {
    asm("fma.rn.f32x2 %0, %1, %2, %0;"
        : "+l"(reinterpret_cast<unsigned long long&>(c))
        : "l"(reinterpret_cast<const unsigned long long&>(a)),
          "l"(reinterpret_cast<const unsigned long long&>(b)));
}
__device__ __forceinline__ uint32_t smem_u32(const void* p) {
    uint32_t a;
    asm("{ .reg .u64 t; cvta.to.shared.u64 t, %1; cvt.u32.u64 %0, t; }" : "=r"(a) : "l"(p));
    return a;
}
__device__ __forceinline__ void cp16(uint32_t dst, const void* src) {
    asm volatile("cp.async.cg.shared.global [%0], [%1], 16;" :: "r"(dst), "l"(src));
}
__device__ __forceinline__ void ldm_x4(uint32_t* r, uint32_t addr) {
    asm volatile("ldmatrix.sync.aligned.m8n8.x4.shared.b16 {%0,%1,%2,%3}, [%4];"
        : "=r"(r[0]), "=r"(r[1]), "=r"(r[2]), "=r"(r[3]) : "r"(addr));
}
__device__ __forceinline__ void ldm_x4t(uint32_t* r, uint32_t addr) {
    asm volatile("ldmatrix.sync.aligned.m8n8.x4.trans.shared.b16 {%0,%1,%2,%3}, [%4];"
        : "=r"(r[0]), "=r"(r[1]), "=r"(r[2]), "=r"(r[3]) : "r"(addr));
}
__device__ __forceinline__ void mma_bf16(float* d, const uint32_t* a, const uint32_t* b) {
    asm volatile("mma.sync.aligned.m16n8k16.row.col.f32.bf16.bf16.f32 "
        "{%0,%1,%2,%3}, {%4,%5,%6,%7}, {%8,%9}, {%0,%1,%2,%3};"
        : "+f"(d[0]), "+f"(d[1]), "+f"(d[2]), "+f"(d[3])
        : "r"(a[0]), "r"(a[1]), "r"(a[2]), "r"(a[3]), "r"(b[0]), "r"(b[1]));
}
__device__ __forceinline__ float tanha(float x) {
    float r;
    asm("tanh.approx.f32 %0, %1;" : "=f"(r) : "f"(x));
    return r;
}
__device__ __forceinline__ uint32_t pack_bf2(float x, float y) {
    __nv_bfloat162 p = __floats2bfloat162_rn(x, y);
    return *reinterpret_cast<uint32_t*>(&p);
}

// ---- K1: fused adj->bf16 + init (xb, h0) ----
__global__ void k_prep(const float* __restrict__ adj, const float* __restrict__ x,
                       const float* __restrict__ W1, const float* __restrict__ b1,
                       const float* __restrict__ b2, float* __restrict__ hout) {
    int idx = blockIdx.x * 256 + threadIdx.x;
    const float4* s = (const float4*)adj + (size_t)idx * 2;
    float4 a = s[0], b = s[1];
    uint4 o;
    o.x = pack_bf2(a.x, a.y);
    o.y = pack_bf2(a.z, a.w);
    o.z = pack_bf2(b.x, b.y);
    o.w = pack_bf2(b.z, b.w);
    ((uint4*)d_adjh)[idx] = o;
    if (idx < BN_TOT * HD) {
        int i = idx >> 6, j = idx & 63;
        float2 xv = ((const float2*)x)[i];
        float v = fmaf(xv.x, W1[2*j], fmaf(xv.y, W1[2*j+1], b1[j])) + b2[j];
        d_xb[idx] = v;
        hout[idx] = fmaxf(v, 0.f);
    }
}

// ---- K2: d_gh[b][node][hd] = bf16(in @ W^T) ----
__global__ void __launch_bounds__(128) k_small(const float* __restrict__ in,
                                               const float* __restrict__ W) {
    __shared__ float hsT[64][36];
    __shared__ float Wt[64][68];
    int tid = threadIdx.x;
    int i0 = blockIdx.x * 32;
    for (int idx = tid; idx < 4096; idx += 128)
        Wt[idx & 63][idx >> 6] = W[idx];
    #pragma unroll
    for (int u = 0; u < 4; ++u) {
        int f = tid + 128 * u;
        int r = f >> 4, kc = (f & 15) * 4;
        float4 v = *(const float4*)&in[(i0 + r) * 64 + kc];
        hsT[kc+0][r] = v.x; hsT[kc+1][r] = v.y; hsT[kc+2][r] = v.z; hsT[kc+3][r] = v.w;
    }
    __syncthreads();
    int r4 = (tid & 7) * 4, j4 = (tid >> 3) * 4;
    float2 acc[4][2];
    #pragma unroll
    for (int rr = 0; rr < 4; ++rr) { acc[rr][0] = make_float2(0,0); acc[rr][1] = make_float2(0,0); }
    #pragma unroll 8
    for (int k = 0; k < 64; ++k) {
        float4 a = *(const float4*)&hsT[k][r4];
        float4 w = *(const float4*)&Wt[k][j4];
        float2 w01 = make_float2(w.x, w.y), w23 = make_float2(w.z, w.w);
        ffma2(acc[0][0], w01, make_float2(a.x, a.x));
        ffma2(acc[0][1], w23, make_float2(a.x, a.x));
        ffma2(acc[1][0], w01, make_float2(a.y, a.y));
        ffma2(acc[1][1], w23, make_float2(a.y, a.y));
        ffma2(acc[2][0], w01, make_float2(a.z, a.z));
        ffma2(acc[2][1], w23, make_float2(a.z, a.z));
        ffma2(acc[3][0], w01, make_float2(a.w, a.w));
        ffma2(acc[3][1], w23, make_float2(a.w, a.w));
    }
    int bb = i0 >> 10, rloc = (i0 & 1023) + r4;
    #pragma unroll
    for (int rr = 0; rr < 4; ++rr) {
        uint2 v;
        v.x = pack_bf2(acc[rr][0].x, acc[rr][0].y);
        v.y = pack_bf2(acc[rr][1].x, acc[rr][1].y);
        *(uint2*)&d_gh[(bb * 1024 + rloc + rr) * 64 + j4] = v;
    }
}

// ---- K3: h = relu(xb + adj@g) via bf16 mma; optional fused A epilogue ----
#define ASZB (128*72*2)
#define BSZB (64*72*2)
#define GSMB (2*ASZB + 2*BSZB)   // 55296 B

__global__ void __launch_bounds__(256, 2) k_gnn_bf(float* __restrict__ hout,
        const float* __restrict__ Wih0, const float* __restrict__ bih0,
        const float* __restrict__ bhh0, int writeA) {
    extern __shared__ char smh[];
    uint32_t sA = smem_u32(smh);
    uint32_t sB = sA + 2 * ASZB;
    int tid = threadIdx.x, lane = tid & 31, w = tid >> 5;
    int mt = blockIdx.x, bb = blockIdx.y;
    const char* Abase = (const char*)d_adjh + ((size_t)bb << 21) + ((size_t)mt << 18);
    const char* Bbase = (const char*)d_gh + ((size_t)bb << 17);

    float acc[8][4];
    #pragma unroll
    for (int j = 0; j < 8; ++j)
        #pragma unroll
        for (int q = 0; q < 4; ++q) acc[j][q] = 0.f;

    auto loadA = [&](int buf, int kt) {
        uint32_t dst = sA + buf * ASZB;
        #pragma unroll
        for (int u = 0; u < 4; ++u) {
            int idx = tid + 256 * u;
            int row = idx >> 3, c = idx & 7;
            cp16(dst + row * 144 + c * 16, Abase + (size_t)row * 2048 + kt * 128 + c * 16);
        }
    };
    auto loadB = [&](int buf, int kt) {
        uint32_t dst = sB + buf * BSZB;
        #pragma unroll
        for (int u = 0; u < 2; ++u) {
            int idx = tid + 256 * u;
            int row = idx >> 3, c = idx & 7;
            cp16(dst + row * 144 + c * 16, Bbase + (size_t)(kt * 64 + row) * 128 + c * 16);
        }
    };

    loadA(0, 0); loadB(0, 0);
    asm volatile("cp.async.commit_group;");

    int arow = lane & 15, acol = (lane >> 4) * 8;
    int q = lane >> 3;
    int brow = (lane & 7) + 8 * (q & 1);
    int bcol = 8 * (q >> 1);
    for (int kt = 0; kt < 16; ++kt) {
        int buf = kt & 1;
        if (kt + 1 < 16) {
            loadA(buf ^ 1, kt + 1);
            loadB(buf ^ 1, kt + 1);
            asm volatile("cp.async.commit_group;");
            asm volatile("cp.async.wait_group 1;" ::: "memory");
        } else {
            asm volatile("cp.async.wait_group 0;" ::: "memory");
        }
        __syncthreads();
        uint32_t a0 = sA + buf * ASZB + (16 * w) * 144;
        uint32_t b0 = sB + buf * BSZB;
        #pragma unroll
        for (int ks = 0; ks < 4; ++ks) {
            uint32_t a[4];
            ldm_x4(a, a0 + arow * 144 + (ks * 16 + acol) * 2);
            uint32_t bf[8][2];
            #pragma unroll
            for (int np = 0; np < 4; ++np) {
                uint32_t t4[4];
                ldm_x4t(t4, b0 + (ks * 16 + brow) * 144 + (np * 16 + bcol) * 2);
                bf[2*np][0] = t4[0]; bf[2*np][1] = t4[1];
                bf[2*np+1][0] = t4[2]; bf[2*np+1][1] = t4[3];
            }
            #pragma unroll
            for (int j = 0; j < 8; ++j)
                mma_bf16(acc[j], a, bf[j]);
        }
        __syncthreads();
    }

    int r = lane >> 2, c2 = (lane & 3) * 2;
    size_t row0 = ((size_t)bb << 10) + ((size_t)mt << 7) + 16 * w;
    #pragma unroll
    for (int j = 0; j < 8; ++j) {
        int col = 8 * j + c2;
        size_t o0 = (row0 + r) * 64 + col;
        float2 xb0 = *(const float2*)&d_xb[o0];
        float2 h0;
        h0.x = fmaxf(xb0.x + acc[j][0], 0.f);
        h0.y = fmaxf(xb0.y + acc[j][1], 0.f);
        *(float2*)&hout[o0] = h0;
        size_t o1 = (row0 + r + 8) * 64 + col;
        float2 xb1 = *(const float2*)&d_xb[o1];
        float2 h1;
        h1.x = fmaxf(xb1.x + acc[j][2], 0.f);
        h1.y = fmaxf(xb1.y + acc[j][3], 0.f);
        *(float2*)&hout[o1] = h1;
    }

    if (writeA) {
        float* hs2 = (float*)smh;             // [64][132]
        float* Wt2 = hs2 + 64 * 132;          // [64][68]
        float* bs2 = Wt2 + 64 * 68;           // [64]
        __syncthreads();
        size_t rowg0 = ((size_t)bb << 10) + ((size_t)mt << 7);
        for (int f = tid; f < 2048; f += 256) {
            int rr = f >> 4, kc = (f & 15) * 4;
            float4 v = *(const float4*)&hout[(rowg0 + rr) * 64 + kc];
            hs2[(kc+0) * 132 + rr] = v.x;
            hs2[(kc+1) * 132 + rr] = v.y;
            hs2[(kc+2) * 132 + rr] = v.z;
            hs2[(kc+3) * 132 + rr] = v.w;
        }
        for (int idx = tid; idx < 4096; idx += 256)
            Wt2[(idx & 63) * 68 + (idx >> 6)] = Wih0[idx];
        if (tid < 64) bs2[tid] = bih0[tid] + bhh0[tid];
        __syncthreads();
        int r4 = (tid & 31) * 4, j8 = (tid >> 5) * 8;
        float2 a2[4][4];
        #pragma unroll
        for (int rr = 0; rr < 4; ++rr)
            #pragma unroll
            for (int p = 0; p < 4; ++p) a2[rr][p] = make_float2(0.f, 0.f);
        #pragma unroll 8
        for (int k = 0; k < 64; ++k) {
            float4 hv = *(const float4*)&hs2[k * 132 + r4];
            float4 wa = *(const float4*)&Wt2[k * 68 + j8];
            float4 wb = *(const float4*)&Wt2[k * 68 + j8 + 4];
            float2 w01 = make_float2(wa.x, wa.y), w23 = make_float2(wa.z, wa.w);
            float2 w45 = make_float2(wb.x, wb.y), w67 = make_float2(wb.z, wb.w);
            #pragma unroll
            for (int rr = 0; rr < 4; ++rr) {
                float hvr = (rr == 0) ? hv.x : (rr == 1) ? hv.y : (rr == 2) ? hv.z : hv.w;
                float2 hd = make_float2(hvr, hvr);
                ffma2(a2[rr][0], w01, hd);
                ffma2(a2[rr][1], w23, hd);
                ffma2(a2[rr][2], w45, hd);
                ffma2(a2[rr][3], w67, hd);
            }
        }
        float* Aout = d_A + ((size_t)bb << 16) + ((size_t)(mt * 128)) * 64;
        #pragma unroll
        for (int rr = 0; rr < 4; ++rr) {
            float4 v1, v2;
            v1.x = a2[rr][0].x + bs2[j8+0];
            v1.y = a2[rr][0].y + bs2[j8+1];
            v1.z = a2[rr][1].x + bs2[j8+2];
            v1.w = a2[rr][1].y + bs2[j8+3];
            v2.x = a2[rr][2].x + bs2[j8+4];
            v2.y = a2[rr][2].y + bs2[j8+5];
            v2.z = a2[rr][3].x + bs2[j8+6];
            v2.w = a2[rr][3].y + bs2[j8+7];
            *(float4*)&Aout[(r4 + rr) * 64 + j8] = v1;
            *(float4*)&Aout[(r4 + rr) * 64 + j8 + 4] = v2;
        }
    }
}

// ---- K4: windowed decoupled scan ----
// G0 (warps 0-1): layer0, named bar 1 (64 thr), window w does t=[8w,8w+8)
// G1 (warps 2-5): layer1, named bar 2 (128 thr), window w does t=[8(w-1),8w)
// G2 (warps 6-7): A prefetch, window w loads t=[8(w+1),8(w+1)+8)
// Block barrier once per window.
__global__ void __launch_bounds__(256, 1) k_scan6(const float* __restrict__ Whh0,
        const float* __restrict__ Wih1, const float* __restrict__ Whh1,
        const float* __restrict__ bih1, const float* __restrict__ bhh1,
        const float* __restrict__ Wt6, const float* __restrict__ bt6) {
    __shared__ float c0ring[32][64];
    __shared__ float Aring[32][64];
    __shared__ float c1p[2][64];
    __shared__ float bsum[64];
    int b = blockIdx.x, tid = threadIdx.x;
    int wid = tid >> 5, lane = tid & 31;
    const float* Ab = d_A + ((size_t)b << 16);

    // zero rings
    for (int i = tid; i < 2048; i += 256) ((float*)c0ring)[i] = 0.f;
    for (int i = tid; i < 128; i += 256) ((float*)c1p)[i] = 0.f;
    if (tid < 64) bsum[tid] = bih1[tid] + bhh1[tid];

    int j = 0, part = 0;
    float2 w[32];
    if (wid < 2) {
        // G0: j = tid (0..63), full-k Whh0 row
        j = tid;
        const float2* wr = (const float2*)(Whh0 + j * 64);
        #pragma unroll
        for (int kk = 0; kk < 32; ++kk) w[kk] = wr[kk];
    } else if (wid < 6) {
        // G1: j per (warp-2, lane&15); part0 = Wih1, part1 = Whh1
        j = (wid - 2) * 16 + (lane & 15);
        part = lane >> 4;
        const float2* wr = (const float2*)((part == 0 ? Wih1 : Whh1) + j * 64);
        #pragma unroll
        for (int kk = 0; kk < 32; ++kk) w[kk] = wr[kk];
    } else {
        // G2: preload window 0 (t = 0..7)
        int tg = tid - 192;
        int tt = tg >> 3, p8 = (tg & 7) * 8;
        float4 v1 = *(const float4*)&Ab[tt * 64 + p8];
        float4 v2 = *(const float4*)&Ab[tt * 64 + p8 + 4];
        *(float4*)&Aring[tt][p8] = v1;
        *(float4*)&Aring[tt][p8 + 4] = v2;
    }
    __syncthreads();

    for (int wnd = 0; wnd < 129; ++wnd) {
        if (wid < 2) {
            if (wnd < 128) {
                #pragma unroll
                for (int i = 0; i < 8; ++i) {
                    int t = wnd * 8 + i;
                    const float4* c4 = (const float4*)&c0ring[(t + 31) & 31][0];
                    float2 a0 = {0,0}, a1 = {0,0}, a2 = {0,0}, a3 = {0,0};
                    #pragma unroll
                    for (int qq = 0; qq < 8; ++qq) {
                        float4 cv0 = c4[2*qq], cv1 = c4[2*qq+1];
                        ffma2(a0, w[4*qq+0], make_float2(cv0.x, cv0.y));
                        ffma2(a1, w[4*qq+1], make_float2(cv0.z, cv0.w));
                        ffma2(a2, w[4*qq+2], make_float2(cv1.x, cv1.y));
                        ffma2(a3, w[4*qq+3], make_float2(cv1.z, cv1.w));
                    }
                    float sx = (a0.x + a1.x) + (a2.x + a3.x);
                    float sy = (a0.y + a1.y) + (a2.y + a3.y);
                    float at = Aring[t & 31][j];
                    c0ring[t & 31][j] = tanha(sx + sy + at);
                    asm volatile("bar.sync 1, 64;" ::: "memory");
                }
            }
        } else if (wid < 6) {
            if (wnd >= 1) {
                #pragma unroll
                for (int i = 0; i < 8; ++i) {
                    int t = (wnd - 1) * 8 + i;
                    const float* csrc = part ? &c1p[t & 1][0] : &c0ring[t & 31][0];
                    const float4* c4 = (const float4*)csrc;
                    float2 a0 = {0,0}, a1 = {0,0}, a2 = {0,0}, a3 = {0,0};
                    #pragma unroll
                    for (int qq = 0; qq < 8; ++qq) {
                        float4 cv0 = c4[2*qq], cv1 = c4[2*qq+1];
                        ffma2(a0, w[4*qq+0], make_float2(cv0.x, cv0.y));
                        ffma2(a1, w[4*qq+1], make_float2(cv0.z, cv0.w));
                        ffma2(a2, w[4*qq+2], make_float2(cv1.x, cv1.y));
                        ffma2(a3, w[4*qq+3], make_float2(cv1.z, cv1.w));
                    }
                    float ps = ((a0.x + a1.x) + (a2.x + a3.x)) + ((a0.y + a1.y) + (a2.y + a3.y));
                    float full = ps + __shfl_xor_sync(0xffffffffu, ps, 16);
                    if (part == 0)
                        c1p[(t + 1) & 1][j] = tanha(full + bsum[j]);
                    asm volatile("bar.sync 2, 128;" ::: "memory");
                }
            }
        } else {
            if (wnd < 127) {
                int tg = tid - 192;
                int tt = (wnd + 1) * 8 + (tg >> 3);
                int p8 = (tg & 7) * 8;
                float4 v1 = *(const float4*)&Ab[tt * 64 + p8];
                float4 v2 = *(const float4*)&Ab[tt * 64 + p8 + 4];
                *(float4*)&Aring[tt & 31][p8] = v1;
                *(float4*)&Aring[tt & 31][p8 + 4] = v2;
            }
        }
        __syncthreads();
    }

    // final c1 is in c1p[0] (last step t=1023 wrote c1p[0])
    if (tid < 64) {
        float acc = bt6[tid];
        const float* cf = c1p[0];
        #pragma unroll 8
        for (int k = 0; k < 64; ++k) acc = fmaf(cf[k], Wt6[tid * 64 + k], acc);
        d_ge[b * 64 + tid] = acc;
    }
}

// ---- K5: gather + R + Y8 ----
__global__ void k_r(const int* __restrict__ label, const int* __restrict__ actions,
                    const float* __restrict__ x, float* __restrict__ Rout) {
    int a = blockIdx.x * 256 + threadIdx.x;
    int b = a >> 9;
    int i0 = actions[2 * a], i1 = actions[2 * a + 1];
    const int* lb = label + (b << 10);
    int a0 = lb[i0], a1 = lb[i1];
    int li = lb[(i0 + 1023) & 1023], ri = lb[(i1 + 1) & 1023];
    int off = b << 10;
    const float2* xv = (const float2*)x;
    float2 y0 = xv[a0 + off], y1 = xv[a1 + off], y2 = xv[li + off], y3 = xv[ri + off];
    float d02x = y0.x - y2.x, d02y = y0.y - y2.y;
    float d13x = y1.x - y3.x, d13y = y1.y - y3.y;
    float d12x = y1.x - y2.x, d12y = y1.y - y2.y;
    float d03x = y0.x - y3.x, d03y = y0.y - y3.y;
    float R = sqrtf(fmaf(d02x, d02x, d02y * d02y)) + sqrtf(fmaf(d13x, d13x, d13y * d13y))
            - sqrtf(fmaf(d12x, d12x, d12y * d12y)) - sqrtf(fmaf(d03x, d03x, d03y * d03y));
    Rout[a] = R;
    float4* Y = (float4*)(d_Y8 + a * 8);
    Y[0] = make_float4(y0.x, y0.y, y1.x, y1.y);
    Y[1] = make_float4(y2.x, y2.y, y3.x, y3.y);
}

// ---- K6: feat + Q ----
__global__ void k_q(const float* __restrict__ WL, const float* __restrict__ bL,
                    const float* __restrict__ Wt5, const float* __restrict__ bt5,
                    const float* __restrict__ R, float* __restrict__ Q) {
    __shared__ float ges[64], WLs[512], bLs[64], w5[65];
    int b = blockIdx.x, a = threadIdx.x;
    if (a < 64) { ges[a] = d_ge[b * 64 + a]; bLs[a] = bL[a]; w5[a] = Wt5[a]; }
    if (a == 64) w5[64] = Wt5[64];
    WLs[a] = WL[a];
    __syncthreads();
    int ba = b * 512 + a;
    float4 y0 = *(const float4*)&d_Y8[ba * 8];
    float4 y1 = *(const float4*)&d_Y8[ba * 8 + 4];
    float y[8] = {y0.x, y0.y, y0.z, y0.w, y1.x, y1.y, y1.z, y1.w};
    float q = 0.f;
    #pragma unroll 8
    for (int jj = 0; jj < 64; ++jj) {
        float f = ges[jj] + bLs[jj];
        #pragma unroll
        for (int m = 0; m < 8; ++m) f = fmaf(y[m], WLs[jj * 8 + m], f);
        q = fmaf(fmaxf(f, 0.f), w5[jj], q);
    }
    Q[ba] = fmaf(R[ba], w5[64], q) + bt5[0];
}

extern "C" void kernel_launch(void* const* d_in, const int* in_sizes, int n_in,
                              void* d_out, int out_size) {
    const float* adj  = (const float*)d_in[0];
    const float* x    = (const float*)d_in[1];
    const int*  label = (const int*)  d_in[2];
    const int*  acts  = (const int*)  d_in[3];
    const float* W1   = (const float*)d_in[4];
    const float* b1   = (const float*)d_in[5];
    const float* W2   = (const float*)d_in[6];
    const float* b2   = (const float*)d_in[7];
    const float* Wih0 = (const float*)d_in[8];
    const float* bih0 = (const float*)d_in[9];
    const float* Whh0 = (const float*)d_in[10];
    const float* bhh0 = (const float*)d_in[11];
    const float* Wih1 = (const float*)d_in[12];
    const float* bih1 = (const float*)d_in[13];
    const float* Whh1 = (const float*)d_in[14];
    const float* bhh1 = (const float*)d_in[15];
    const float* Wt6  = (const float*)d_in[16];
    const float* bt6  = (const float*)d_in[17];
    const float* WL   = (const float*)d_in[18];
    const float* bL   = (const float*)d_in[19];
    const float* Wt5  = (const float*)d_in[20];
    const float* bt5  = (const float*)d_in[21];

    float* out  = (float*)d_out;
    float* Rout = out;
    float* hout = out + 16384;
    float* Qout = out + 16384 + BN_TOT * HD;

    cudaFuncSetAttribute(k_gnn_bf, cudaFuncAttributeMaxDynamicSharedMemorySize, GSMB);

    k_prep<<<16384, 256>>>(adj, x, W1, b1, b2, hout);                     // 1
    k_small<<<1024, 128>>>(hout, W2);                                     // 2
    k_gnn_bf<<<dim3(8, 32), 256, GSMB>>>(hout, Wih0, bih0, bhh0, 0);      // 3
    k_small<<<1024, 128>>>(hout, W2);                                     // 4
    k_gnn_bf<<<dim3(8, 32), 256, GSMB>>>(hout, Wih0, bih0, bhh0, 1);      // 5
    k_scan6<<<32, 256>>>(Whh0, Wih1, Whh1, bih1, bhh1, Wt6, bt6);         // 6
    k_r<<<64, 256>>>(label, acts, x, Rout);                               // 7
    k_q<<<32, 512>>>(WL, bL, Wt5, bt5, Rout, Qout);                       // 8
}

// round 15
// speedup vs baseline: 1.6308x; 1.0265x over previous
#include <cuda_runtime.h>
#include <cuda_bf16.h>
#include <cstdint>

#define HD 64
#define NB 32
#define BN_TOT (NB*1024)
#define NA_TOT 16384

__device__ float d_xb[BN_TOT*HD];
__device__ float d_A [BN_TOT*HD];   // [b][t][j]
__device__ float d_Y8[NA_TOT*8];
__device__ float d_ge[NB*HD];
__device__ __align__(16) unsigned short d_adjh[NB*1024*1024];  // adj bf16
__device__ __align__(16) unsigned short d_gh[BN_TOT*HD];       // g bf16 [b][node][hd]

__device__ __forceinline__ void ffma2(float2 &c, const float2 a, const float2 b) {
    asm("fma.rn.f32x2 %0, %1, %2, %0;"
        : "+l"(reinterpret_cast<unsigned long long&>(c))
        : "l"(reinterpret_cast<const unsigned long long&>(a)),
          "l"(reinterpret_cast<const unsigned long long&>(b)));
}
__device__ __forceinline__ uint32_t smem_u32(const void* p) {
    uint32_t a;
    asm("{ .reg .u64 t; cvta.to.shared.u64 t, %1; cvt.u32.u64 %0, t; }" : "=r"(a) : "l"(p));
    return a;
}
__device__ __forceinline__ void cp16(uint32_t dst, const void* src) {
    asm volatile("cp.async.cg.shared.global [%0], [%1], 16;" :: "r"(dst), "l"(src));
}
__device__ __forceinline__ void ldm_x4(uint32_t* r, uint32_t addr) {
    asm volatile("ldmatrix.sync.aligned.m8n8.x4.shared.b16 {%0,%1,%2,%3}, [%4];"
        : "=r"(r[0]), "=r"(r[1]), "=r"(r[2]), "=r"(r[3]) : "r"(addr));
}
__device__ __forceinline__ void ldm_x4t(uint32_t* r, uint32_t addr) {
    asm volatile("ldmatrix.sync.aligned.m8n8.x4.trans.shared.b16 {%0,%1,%2,%3}, [%4];"
        : "=r"(r[0]), "=r"(r[1]), "=r"(r[2]), "=r"(r[3]) : "r"(addr));
}
__device__ __forceinline__ void mma_bf16(float* d, const uint32_t* a, const uint32_t* b) {
    asm volatile("mma.sync.aligned.m16n8k16.row.col.f32.bf16.bf16.f32 "
        "{%0,%1,%2,%3}, {%4,%5,%6,%7}, {%8,%9}, {%0,%1,%2,%3};"
        : "+f"(d[0]), "+f"(d[1]), "+f"(d[2]), "+f"(d[3])
        : "r"(a[0]), "r"(a[1]), "r"(a[2]), "r"(a[3]), "r"(b[0]), "r"(b[1]));
}
__device__ __forceinline__ float tanha(float x) {
    float r;
    asm("tanh.approx.f32 %0, %1;" : "=f"(r) : "f"(x));
    return r;
}
__device__ __forceinline__ uint32_t pack_bf2(float x, float y) {
    __nv_bfloat162 p = __floats2bfloat162_rn(x, y);
    return *reinterpret_cast<uint32_t*>(&p);
}

// ---- K1: fused adj->bf16 + init (xb, h0) ----
__global__ void k_prep(const float* __restrict__ adj, const float* __restrict__ x,
                       const float* __restrict__ W1, const float* __restrict__ b1,
                       const float* __restrict__ b2, float* __restrict__ hout) {
    int idx = blockIdx.x * 256 + threadIdx.x;
    const float4* s = (const float4*)adj + (size_t)idx * 2;
    float4 a = s[0], b = s[1];
    uint4 o;
    o.x = pack_bf2(a.x, a.y);
    o.y = pack_bf2(a.z, a.w);
    o.z = pack_bf2(b.x, b.y);
    o.w = pack_bf2(b.z, b.w);
    ((uint4*)d_adjh)[idx] = o;
    if (idx < BN_TOT * HD) {
        int i = idx >> 6, j = idx & 63;
        float2 xv = ((const float2*)x)[i];
        float v = fmaf(xv.x, W1[2*j], fmaf(xv.y, W1[2*j+1], b1[j])) + b2[j];
        d_xb[idx] = v;
        hout[idx] = fmaxf(v, 0.f);
    }
}

// ---- K2: d_gh[b][node][hd] = bf16(in @ W^T) ----
__global__ void __launch_bounds__(128) k_small(const float* __restrict__ in,
                                               const float* __restrict__ W) {
    __shared__ float hsT[64][36];
    __shared__ float Wt[64][68];
    int tid = threadIdx.x;
    int i0 = blockIdx.x * 32;
    for (int idx = tid; idx < 4096; idx += 128)
        Wt[idx & 63][idx >> 6] = W[idx];
    #pragma unroll
    for (int u = 0; u < 4; ++u) {
        int f = tid + 128 * u;
        int r = f >> 4, kc = (f & 15) * 4;
        float4 v = *(const float4*)&in[(i0 + r) * 64 + kc];
        hsT[kc+0][r] = v.x; hsT[kc+1][r] = v.y; hsT[kc+2][r] = v.z; hsT[kc+3][r] = v.w;
    }
    __syncthreads();
    int r4 = (tid & 7) * 4, j4 = (tid >> 3) * 4;
    float2 acc[4][2];
    #pragma unroll
    for (int rr = 0; rr < 4; ++rr) { acc[rr][0] = make_float2(0,0); acc[rr][1] = make_float2(0,0); }
    #pragma unroll 8
    for (int k = 0; k < 64; ++k) {
        float4 a = *(const float4*)&hsT[k][r4];
        float4 w = *(const float4*)&Wt[k][j4];
        float2 w01 = make_float2(w.x, w.y), w23 = make_float2(w.z, w.w);
        ffma2(acc[0][0], w01, make_float2(a.x, a.x));
        ffma2(acc[0][1], w23, make_float2(a.x, a.x));
        ffma2(acc[1][0], w01, make_float2(a.y, a.y));
        ffma2(acc[1][1], w23, make_float2(a.y, a.y));
        ffma2(acc[2][0], w01, make_float2(a.z, a.z));
        ffma2(acc[2][1], w23, make_float2(a.z, a.z));
        ffma2(acc[3][0], w01, make_float2(a.w, a.w));
        ffma2(acc[3][1], w23, make_float2(a.w, a.w));
    }
    int bb = i0 >> 10, rloc = (i0 & 1023) + r4;
    #pragma unroll
    for (int rr = 0; rr < 4; ++rr) {
        uint2 v;
        v.x = pack_bf2(acc[rr][0].x, acc[rr][0].y);
        v.y = pack_bf2(acc[rr][1].x, acc[rr][1].y);
        *(uint2*)&d_gh[(bb * 1024 + rloc + rr) * 64 + j4] = v;
    }
}

// ---- K3: h = relu(xb + adj@g) via bf16 mma, 3-stage pipeline; optional fused A epilogue ----
#define ASZB (128*72*2)
#define BSZB (64*72*2)
#define GSMB (3*(ASZB+BSZB))   // 82944 B

__global__ void __launch_bounds__(256, 2) k_gnn_bf(float* __restrict__ hout,
        const float* __restrict__ Wih0, const float* __restrict__ bih0,
        const float* __restrict__ bhh0, int writeA) {
    extern __shared__ char smh[];
    uint32_t sA = smem_u32(smh);
    uint32_t sB = sA + 3 * ASZB;
    int tid = threadIdx.x, lane = tid & 31, w = tid >> 5;
    int mt = blockIdx.x, bb = blockIdx.y;
    const char* Abase = (const char*)d_adjh + ((size_t)bb << 21) + ((size_t)mt << 18);
    const char* Bbase = (const char*)d_gh + ((size_t)bb << 17);

    float acc[8][4];
    #pragma unroll
    for (int j = 0; j < 8; ++j)
        #pragma unroll
        for (int q = 0; q < 4; ++q) acc[j][q] = 0.f;

    auto loadA = [&](int buf, int kt) {
        uint32_t dst = sA + buf * ASZB;
        #pragma unroll
        for (int u = 0; u < 4; ++u) {
            int idx = tid + 256 * u;
            int row = idx >> 3, c = idx & 7;
            cp16(dst + row * 144 + c * 16, Abase + (size_t)row * 2048 + kt * 128 + c * 16);
        }
    };
    auto loadB = [&](int buf, int kt) {
        uint32_t dst = sB + buf * BSZB;
        #pragma unroll
        for (int u = 0; u < 2; ++u) {
            int idx = tid + 256 * u;
            int row = idx >> 3, c = idx & 7;
            cp16(dst + row * 144 + c * 16, Bbase + (size_t)(kt * 64 + row) * 128 + c * 16);
        }
    };

    loadA(0, 0); loadB(0, 0);
    asm volatile("cp.async.commit_group;");
    loadA(1, 1); loadB(1, 1);
    asm volatile("cp.async.commit_group;");

    int arow = lane & 15, acol = (lane >> 4) * 8;
    int q = lane >> 3;
    int brow = (lane & 7) + 8 * (q & 1);
    int bcol = 8 * (q >> 1);
    for (int kt = 0; kt < 16; ++kt) {
        int buf = kt % 3;
        // groups in flight at this point: kt, kt+1 (kt+2 not yet committed).
        // Need group kt complete -> allow at most 1 outstanding (or 0 on last iter).
        if (kt < 15) {
            asm volatile("cp.async.wait_group 1;" ::: "memory");
        } else {
            asm volatile("cp.async.wait_group 0;" ::: "memory");
        }
        __syncthreads();
        if (kt + 2 < 16) {
            int nb = (kt + 2) % 3;
            loadA(nb, kt + 2);
            loadB(nb, kt + 2);
            asm volatile("cp.async.commit_group;");
        }
        uint32_t a0 = sA + buf * ASZB + (16 * w) * 144;
        uint32_t b0 = sB + buf * BSZB;
        #pragma unroll
        for (int ks = 0; ks < 4; ++ks) {
            uint32_t a[4];
            ldm_x4(a, a0 + arow * 144 + (ks * 16 + acol) * 2);
            uint32_t bf[8][2];
            #pragma unroll
            for (int np = 0; np < 4; ++np) {
                uint32_t t4[4];
                ldm_x4t(t4, b0 + (ks * 16 + brow) * 144 + (np * 16 + bcol) * 2);
                bf[2*np][0] = t4[0]; bf[2*np][1] = t4[1];
                bf[2*np+1][0] = t4[2]; bf[2*np+1][1] = t4[3];
            }
            #pragma unroll
            for (int j = 0; j < 8; ++j)
                mma_bf16(acc[j], a, bf[j]);
        }
    }

    int r = lane >> 2, c2 = (lane & 3) * 2;
    size_t row0 = ((size_t)bb << 10) + ((size_t)mt << 7) + 16 * w;
    #pragma unroll
    for (int j = 0; j < 8; ++j) {
        int col = 8 * j + c2;
        size_t o0 = (row0 + r) * 64 + col;
        float2 xb0 = *(const float2*)&d_xb[o0];
        float2 h0;
        h0.x = fmaxf(xb0.x + acc[j][0], 0.f);
        h0.y = fmaxf(xb0.y + acc[j][1], 0.f);
        *(float2*)&hout[o0] = h0;
        size_t o1 = (row0 + r + 8) * 64 + col;
        float2 xb1 = *(const float2*)&d_xb[o1];
        float2 h1;
        h1.x = fmaxf(xb1.x + acc[j][2], 0.f);
        h1.y = fmaxf(xb1.y + acc[j][3], 0.f);
        *(float2*)&hout[o1] = h1;
    }

    if (writeA) {
        float* hs2 = (float*)smh;             // [64][132]
        float* Wt2 = hs2 + 64 * 132;          // [64][68]
        float* bs2 = Wt2 + 64 * 68;           // [64]
        __syncthreads();
        size_t rowg0 = ((size_t)bb << 10) + ((size_t)mt << 7);
        for (int f = tid; f < 2048; f += 256) {
            int rr = f >> 4, kc = (f & 15) * 4;
            float4 v = *(const float4*)&hout[(rowg0 + rr) * 64 + kc];
            hs2[(kc+0) * 132 + rr] = v.x;
            hs2[(kc+1) * 132 + rr] = v.y;
            hs2[(kc+2) * 132 + rr] = v.z;
            hs2[(kc+3) * 132 + rr] = v.w;
        }
        for (int idx = tid; idx < 4096; idx += 256)
            Wt2[(idx & 63) * 68 + (idx >> 6)] = Wih0[idx];
        if (tid < 64) bs2[tid] = bih0[tid] + bhh0[tid];
        __syncthreads();
        int r4 = (tid & 31) * 4, j8 = (tid >> 5) * 8;
        float2 a2[4][4];
        #pragma unroll
        for (int rr = 0; rr < 4; ++rr)
            #pragma unroll
            for (int p = 0; p < 4; ++p) a2[rr][p] = make_float2(0.f, 0.f);
        #pragma unroll 8
        for (int k = 0; k < 64; ++k) {
            float4 hv = *(const float4*)&hs2[k * 132 + r4];
            float4 wa = *(const float4*)&Wt2[k * 68 + j8];
            float4 wb = *(const float4*)&Wt2[k * 68 + j8 + 4];
            float2 w01 = make_float2(wa.x, wa.y), w23 = make_float2(wa.z, wa.w);
            float2 w45 = make_float2(wb.x, wb.y), w67 = make_float2(wb.z, wb.w);
            #pragma unroll
            for (int rr = 0; rr < 4; ++rr) {
                float hvr = (rr == 0) ? hv.x : (rr == 1) ? hv.y : (rr == 2) ? hv.z : hv.w;
                float2 hd = make_float2(hvr, hvr);
                ffma2(a2[rr][0], w01, hd);
                ffma2(a2[rr][1], w23, hd);
                ffma2(a2[rr][2], w45, hd);
                ffma2(a2[rr][3], w67, hd);
            }
        }
        float* Aout = d_A + ((size_t)bb << 16) + ((size_t)(mt * 128)) * 64;
        #pragma unroll
        for (int rr = 0; rr < 4; ++rr) {
            float4 v1, v2;
            v1.x = a2[rr][0].x + bs2[j8+0];
            v1.y = a2[rr][0].y + bs2[j8+1];
            v1.z = a2[rr][1].x + bs2[j8+2];
            v1.w = a2[rr][1].y + bs2[j8+3];
            v2.x = a2[rr][2].x + bs2[j8+4];
            v2.y = a2[rr][2].y + bs2[j8+5];
            v2.z = a2[rr][3].x + bs2[j8+6];
            v2.w = a2[rr][3].y + bs2[j8+7];
            *(float4*)&Aout[(r4 + rr) * 64 + j8] = v1;
            *(float4*)&Aout[(r4 + rr) * 64 + j8 + 4] = v2;
        }
    }
}

// ---- K4: windowed decoupled scan, batched layer-1 input ----
// G0  (warps 0-1): layer0 serial, bar 1 (64 thr), window w: t=[8w,8w+8)
// G1b (warps 2-3): u[t] = Wih1.c0[t] + bsum, batch for window w-1 (no inner bar)
// G1a (warps 4-5): c1[t] = tanh(Whh1.c1[t-1] + u[t]) serial, bar 2 (64 thr), window w-2
// G2  (warps 6-7): A prefetch for window w+1
__global__ void __launch_bounds__(256, 1) k_scan7(const float* __restrict__ Whh0,
        const float* __restrict__ Wih1, const float* __restrict__ Whh1,
        const float* __restrict__ bih1, const float* __restrict__ bhh1,
        const float* __restrict__ Wt6, const float* __restrict__ bt6) {
    __shared__ float c0ring[32][64];
    __shared__ float Aring[32][64];
    __shared__ float uring[16][64];
    __shared__ float c1p[2][64];
    __shared__ float bsum[64];
    int b = blockIdx.x, tid = threadIdx.x;
    int wid = tid >> 5;
    const float* Ab = d_A + ((size_t)b << 16);

    for (int i = tid; i < 2048; i += 256) ((float*)c0ring)[i] = 0.f;
    for (int i = tid; i < 128; i += 256) ((float*)c1p)[i] = 0.f;
    if (tid < 64) bsum[tid] = bih1[tid] + bhh1[tid];

    int j = 0;
    float2 w[32];
    if (wid < 2) {
        j = tid;
        const float2* wr = (const float2*)(Whh0 + j * 64);
        #pragma unroll
        for (int kk = 0; kk < 32; ++kk) w[kk] = wr[kk];
    } else if (wid < 4) {
        j = tid - 64;
        const float2* wr = (const float2*)(Wih1 + j * 64);
        #pragma unroll
        for (int kk = 0; kk < 32; ++kk) w[kk] = wr[kk];
    } else if (wid < 6) {
        j = tid - 128;
        const float2* wr = (const float2*)(Whh1 + j * 64);
        #pragma unroll
        for (int kk = 0; kk < 32; ++kk) w[kk] = wr[kk];
    } else {
        int tg = tid - 192;
        int tt = tg >> 3, p8 = (tg & 7) * 8;
        float4 v1 = *(const float4*)&Ab[tt * 64 + p8];
        float4 v2 = *(const float4*)&Ab[tt * 64 + p8 + 4];
        *(float4*)&Aring[tt][p8] = v1;
        *(float4*)&Aring[tt][p8 + 4] = v2;
    }
    __syncthreads();

    for (int wnd = 0; wnd < 130; ++wnd) {
        if (wid < 2) {
            if (wnd < 128) {
                #pragma unroll
                for (int i = 0; i < 8; ++i) {
                    int t = wnd * 8 + i;
                    const float4* c4 = (const float4*)&c0ring[(t + 31) & 31][0];
                    float2 a0 = {0,0}, a1 = {0,0}, a2 = {0,0}, a3 = {0,0};
                    #pragma unroll
                    for (int qq = 0; qq < 8; ++qq) {
                        float4 cv0 = c4[2*qq], cv1 = c4[2*qq+1];
                        ffma2(a0, w[4*qq+0], make_float2(cv0.x, cv0.y));
                        ffma2(a1, w[4*qq+1], make_float2(cv0.z, cv0.w));
                        ffma2(a2, w[4*qq+2], make_float2(cv1.x, cv1.y));
                        ffma2(a3, w[4*qq+3], make_float2(cv1.z, cv1.w));
                    }
                    float sx = (a0.x + a1.x) + (a2.x + a3.x);
                    float sy = (a0.y + a1.y) + (a2.y + a3.y);
                    float at = Aring[t & 31][j];
                    c0ring[t & 31][j] = tanha(sx + sy + at);
                    asm volatile("bar.sync 1, 64;" ::: "memory");
                }
            }
        } else if (wid < 4) {
            if (wnd >= 1 && wnd <= 128) {
                #pragma unroll
                for (int i = 0; i < 8; ++i) {
                    int t = (wnd - 1) * 8 + i;
                    const float4* c4 = (const float4*)&c0ring[t & 31][0];
                    float2 a0 = {0,0}, a1 = {0,0}, a2 = {0,0}, a3 = {0,0};
                    #pragma unroll
                    for (int qq = 0; qq < 8; ++qq) {
                        float4 cv0 = c4[2*qq], cv1 = c4[2*qq+1];
                        ffma2(a0, w[4*qq+0], make_float2(cv0.x, cv0.y));
                        ffma2(a1, w[4*qq+1], make_float2(cv0.z, cv0.w));
                        ffma2(a2, w[4*qq+2], make_float2(cv1.x, cv1.y));
                        ffma2(a3, w[4*qq+3], make_float2(cv1.z, cv1.w));
                    }
                    float ps = ((a0.x + a1.x) + (a2.x + a3.x)) + ((a0.y + a1.y) + (a2.y + a3.y));
                    uring[t & 15][j] = ps + bsum[j];
                }
            }
        } else if (wid < 6) {
            if (wnd >= 2) {
                #pragma unroll
                for (int i = 0; i < 8; ++i) {
                    int t = (wnd - 2) * 8 + i;
                    const float4* c4 = (const float4*)&c1p[(t + 1) & 1][0];
                    float2 a0 = {0,0}, a1 = {0,0}, a2 = {0,0}, a3 = {0,0};
                    #pragma unroll
                    for (int qq = 0; qq < 8; ++qq) {
                        float4 cv0 = c4[2*qq], cv1 = c4[2*qq+1];
                        ffma2(a0, w[4*qq+0], make_float2(cv0.x, cv0.y));
                        ffma2(a1, w[4*qq+1], make_float2(cv0.z, cv0.w));
                        ffma2(a2, w[4*qq+2], make_float2(cv1.x, cv1.y));
                        ffma2(a3, w[4*qq+3], make_float2(cv1.z, cv1.w));
                    }
                    float ps = ((a0.x + a1.x) + (a2.x + a3.x)) + ((a0.y + a1.y) + (a2.y + a3.y));
                    c1p[t & 1][j] = tanha(ps + uring[t & 15][j]);
                    asm volatile("bar.sync 2, 64;" ::: "memory");
                }
            }
        } else {
            if (wnd < 127) {
                int tg = tid - 192;
                int tt = (wnd + 1) * 8 + (tg >> 3);
                int p8 = (tg & 7) * 8;
                float4 v1 = *(const float4*)&Ab[tt * 64 + p8];
                float4 v2 = *(const float4*)&Ab[tt * 64 + p8 + 4];
                *(float4*)&Aring[tt & 31][p8] = v1;
                *(float4*)&Aring[tt & 31][p8 + 4] = v2;
            }
        }
        __syncthreads();
    }

    // final c1 at t=1023 -> c1p[1]
    if (tid < 64) {
        float acc = bt6[tid];
        const float* cf = c1p[1];
        #pragma unroll 8
        for (int k = 0; k < 64; ++k) acc = fmaf(cf[k], Wt6[tid * 64 + k], acc);
        d_ge[b * 64 + tid] = acc;
    }
}

// ---- K5: gather + R + Y8 ----
__global__ void k_r(const int* __restrict__ label, const int* __restrict__ actions,
                    const float* __restrict__ x, float* __restrict__ Rout) {
    int a = blockIdx.x * 256 + threadIdx.x;
    int b = a >> 9;
    int i0 = actions[2 * a], i1 = actions[2 * a + 1];
    const int* lb = label + (b << 10);
    int a0 = lb[i0], a1 = lb[i1];
    int li = lb[(i0 + 1023) & 1023], ri = lb[(i1 + 1) & 1023];
    int off = b << 10;
    const float2* xv = (const float2*)x;
    float2 y0 = xv[a0 + off], y1 = xv[a1 + off], y2 = xv[li + off], y3 = xv[ri + off];
    float d02x = y0.x - y2.x, d02y = y0.y - y2.y;
    float d13x = y1.x - y3.x, d13y = y1.y - y3.y;
    float d12x = y1.x - y2.x, d12y = y1.y - y2.y;
    float d03x = y0.x - y3.x, d03y = y0.y - y3.y;
    float R = sqrtf(fmaf(d02x, d02x, d02y * d02y)) + sqrtf(fmaf(d13x, d13x, d13y * d13y))
            - sqrtf(fmaf(d12x, d12x, d12y * d12y)) - sqrtf(fmaf(d03x, d03x, d03y * d03y));
    Rout[a] = R;
    float4* Y = (float4*)(d_Y8 + a * 8);
    Y[0] = make_float4(y0.x, y0.y, y1.x, y1.y);
    Y[1] = make_float4(y2.x, y2.y, y3.x, y3.y);
}

// ---- K6: feat + Q ----
__global__ void k_q(const float* __restrict__ WL, const float* __restrict__ bL,
                    const float* __restrict__ Wt5, const float* __restrict__ bt5,
                    const float* __restrict__ R, float* __restrict__ Q) {
    __shared__ float ges[64], WLs[512], bLs[64], w5[65];
    int b = blockIdx.x, a = threadIdx.x;
    if (a < 64) { ges[a] = d_ge[b * 64 + a]; bLs[a] = bL[a]; w5[a] = Wt5[a]; }
    if (a == 64) w5[64] = Wt5[64];
    WLs[a] = WL[a];
    __syncthreads();
    int ba = b * 512 + a;
    float4 y0 = *(const float4*)&d_Y8[ba * 8];
    float4 y1 = *(const float4*)&d_Y8[ba * 8 + 4];
    float y[8] = {y0.x, y0.y, y0.z, y0.w, y1.x, y1.y, y1.z, y1.w};
    float q = 0.f;
    #pragma unroll 8
    for (int jj = 0; jj < 64; ++jj) {
        float f = ges[jj] + bLs[jj];
        #pragma unroll
        for (int m = 0; m < 8; ++m) f = fmaf(y[m], WLs[jj * 8 + m], f);
        q = fmaf(fmaxf(f, 0.f), w5[jj], q);
    }
    Q[ba] = fmaf(R[ba], w5[64], q) + bt5[0];
}

extern "C" void kernel_launch(void* const* d_in, const int* in_sizes, int n_in,
                              void* d_out, int out_size) {
    const float* adj  = (const float*)d_in[0];
    const float* x    = (const float*)d_in[1];
    const int*  label = (const int*)  d_in[2];
    const int*  acts  = (const int*)  d_in[3];
    const float* W1   = (const float*)d_in[4];
    const float* b1   = (const float*)d_in[5];
    const float* W2   = (const float*)d_in[6];
    const float* b2   = (const float*)d_in[7];
    const float* Wih0 = (const float*)d_in[8];
    const float* bih0 = (const float*)d_in[9];
    const float* Whh0 = (const float*)d_in[10];
    const float* bhh0 = (const float*)d_in[11];
    const float* Wih1 = (const float*)d_in[12];
    const float* bih1 = (const float*)d_in[13];
    const float* Whh1 = (const float*)d_in[14];
    const float* bhh1 = (const float*)d_in[15];
    const float* Wt6  = (const float*)d_in[16];
    const float* bt6  = (const float*)d_in[17];
    const float* WL   = (const float*)d_in[18];
    const float* bL   = (const float*)d_in[19];
    const float* Wt5  = (const float*)d_in[20];
    const float* bt5  = (const float*)d_in[21];

    float* out  = (float*)d_out;
    float* Rout = out;
    float* hout = out + 16384;
    float* Qout = out + 16384 + BN_TOT * HD;

    cudaFuncSetAttribute(k_gnn_bf, cudaFuncAttributeMaxDynamicSharedMemorySize, GSMB);

    k_prep<<<16384, 256>>>(adj, x, W1, b1, b2, hout);                     // 1
    k_small<<<1024, 128>>>(hout, W2);                                     // 2
    k_gnn_bf<<<dim3(8, 32), 256, GSMB>>>(hout, Wih0, bih0, bhh0, 0);      // 3
    k_small<<<1024, 128>>>(hout, W2);                                     // 4
    k_gnn_bf<<<dim3(8, 32), 256, GSMB>>>(hout, Wih0, bih0, bhh0, 1);      // 5
    k_scan7<<<32, 256>>>(Whh0, Wih1, Whh1, bih1, bhh1, Wt6, bt6);         // 6
    k_r<<<64, 256>>>(label, acts, x, Rout);                               // 7
    k_q<<<32, 512>>>(WL, bL, Wt5, bt5, Rout, Qout);                       // 8
}